// round 1
// baseline (speedup 1.0000x reference)
#include <cuda_runtime.h>
#include <cstddef>

// ---------------------------------------------------------------------------
// SelfAttention: x(16,1024,1024) f32, three (1024,1024) weights.
//   ip = x^T (B,D,N); vk/vq/vv = ip @ w; kq = vk @ vq^T / 32;
//   sm = softmax(kq, -1); out = (sm @ vv) transposed back to (B,N,D).
//
// All five GEMMs are expressed uniformly as C[i][j] = sum_k A[k][i]*B[k][j]
// with 1024x1024 matrices, row-major C. Template flags say whether A/B are
// stored K-major ("direct") or row-major (needs smem transpose on load).
// ---------------------------------------------------------------------------

#define L 1024
#define BATCH 16
#define BM 128
#define BN 128
#define BK 16

// 4 x 64MB scratch (device globals: allowed; cudaMalloc is not).
__device__ __align__(128) float g_vk[(size_t)BATCH * L * L];
__device__ __align__(128) float g_vq[(size_t)BATCH * L * L];
__device__ __align__(128) float g_vv[(size_t)BATCH * L * L];
__device__ __align__(128) float g_kq[(size_t)BATCH * L * L];

// ATRANS=false: A stored [k][i] (i contiguous)  -> direct coalesced load
// ATRANS=true : A stored [i][k] (k contiguous)  -> transpose into smem
template <bool ATRANS, bool BTRANS>
__global__ __launch_bounds__(256, 2)
void gemm_kernel(const float* __restrict__ A, size_t strideA,
                 const float* __restrict__ B, size_t strideB,
                 float* __restrict__ C, size_t strideC,
                 float scale)
{
    A += (size_t)blockIdx.z * strideA;
    B += (size_t)blockIdx.z * strideB;
    C += (size_t)blockIdx.z * strideC;

    __shared__ float As[BK][BM + 4];
    __shared__ float Bs[BK][BN + 4];

    const int tid = threadIdx.x;
    const int tx = tid & 15;          // -> C columns
    const int ty = tid >> 4;          // -> C rows
    const int i0 = blockIdx.y * BM;
    const int j0 = blockIdx.x * BN;

    float acc[8][8];
#pragma unroll
    for (int u = 0; u < 8; u++)
#pragma unroll
        for (int v = 0; v < 8; v++) acc[u][v] = 0.0f;

    for (int k0 = 0; k0 < L; k0 += BK) {
        // ---- load A tile into As[k][i] ----
        if (ATRANS) {
            const int r  = tid >> 2;            // 0..63
            const int k4 = (tid & 3) * 4;       // 0,4,8,12
#pragma unroll
            for (int it = 0; it < 2; it++) {
                const int i = r + it * 64;
                float4 v = *reinterpret_cast<const float4*>(
                    &A[(size_t)(i0 + i) * L + k0 + k4]);
                As[k4 + 0][i] = v.x;
                As[k4 + 1][i] = v.y;
                As[k4 + 2][i] = v.z;
                As[k4 + 3][i] = v.w;
            }
        } else {
            const int kr = tid >> 5;            // 0..7
            const int c4 = (tid & 31) * 4;      // 0..124
#pragma unroll
            for (int it = 0; it < 2; it++) {
                const int k = kr + it * 8;
                float4 v = *reinterpret_cast<const float4*>(
                    &A[(size_t)(k0 + k) * L + i0 + c4]);
                *reinterpret_cast<float4*>(&As[k][c4]) = v;
            }
        }
        // ---- load B tile into Bs[k][j] ----
        if (BTRANS) {
            const int r  = tid >> 2;
            const int k4 = (tid & 3) * 4;
#pragma unroll
            for (int it = 0; it < 2; it++) {
                const int j = r + it * 64;
                float4 v = *reinterpret_cast<const float4*>(
                    &B[(size_t)(j0 + j) * L + k0 + k4]);
                Bs[k4 + 0][j] = v.x;
                Bs[k4 + 1][j] = v.y;
                Bs[k4 + 2][j] = v.z;
                Bs[k4 + 3][j] = v.w;
            }
        } else {
            const int kr = tid >> 5;
            const int c4 = (tid & 31) * 4;
#pragma unroll
            for (int it = 0; it < 2; it++) {
                const int k = kr + it * 8;
                float4 v = *reinterpret_cast<const float4*>(
                    &B[(size_t)(k0 + k) * L + j0 + c4]);
                *reinterpret_cast<float4*>(&Bs[k][c4]) = v;
            }
        }
        __syncthreads();

        // ---- 8x8 micro-tile FMA (split halves: conflict-free LDS.128) ----
#pragma unroll
        for (int kk = 0; kk < BK; kk++) {
            float4 a0 = *reinterpret_cast<const float4*>(&As[kk][ty * 4]);
            float4 a1 = *reinterpret_cast<const float4*>(&As[kk][ty * 4 + 64]);
            float4 b0 = *reinterpret_cast<const float4*>(&Bs[kk][tx * 4]);
            float4 b1 = *reinterpret_cast<const float4*>(&Bs[kk][tx * 4 + 64]);
            float a[8] = {a0.x, a0.y, a0.z, a0.w, a1.x, a1.y, a1.z, a1.w};
            float b[8] = {b0.x, b0.y, b0.z, b0.w, b1.x, b1.y, b1.z, b1.w};
#pragma unroll
            for (int u = 0; u < 8; u++)
#pragma unroll
                for (int v = 0; v < 8; v++) acc[u][v] += a[u] * b[v];
        }
        __syncthreads();
    }

    // ---- store (two float4 per row) ----
#pragma unroll
    for (int u = 0; u < 8; u++) {
        const int i = i0 + ((u < 4) ? (ty * 4 + u) : (64 + ty * 4 + (u - 4)));
        float4 o0 = make_float4(acc[u][0] * scale, acc[u][1] * scale,
                                acc[u][2] * scale, acc[u][3] * scale);
        float4 o1 = make_float4(acc[u][4] * scale, acc[u][5] * scale,
                                acc[u][6] * scale, acc[u][7] * scale);
        *reinterpret_cast<float4*>(&C[(size_t)i * L + j0 + tx * 4])      = o0;
        *reinterpret_cast<float4*>(&C[(size_t)i * L + j0 + 64 + tx * 4]) = o1;
    }
}

// In-place row softmax: one block (256 threads) per 1024-float row.
__global__ __launch_bounds__(256)
void softmax_kernel(float* __restrict__ data)
{
    float* row = data + (size_t)blockIdx.x * L;
    const int tid = threadIdx.x;
    float4 v = *reinterpret_cast<const float4*>(&row[tid * 4]);

    __shared__ float red[8];
    const int lane = tid & 31, wid = tid >> 5;

    // max
    float m = fmaxf(fmaxf(v.x, v.y), fmaxf(v.z, v.w));
#pragma unroll
    for (int o = 16; o; o >>= 1) m = fmaxf(m, __shfl_xor_sync(0xffffffffu, m, o));
    if (lane == 0) red[wid] = m;
    __syncthreads();
    m = red[0];
#pragma unroll
    for (int w = 1; w < 8; w++) m = fmaxf(m, red[w]);
    __syncthreads();

    // exp + sum
    v.x = expf(v.x - m); v.y = expf(v.y - m);
    v.z = expf(v.z - m); v.w = expf(v.w - m);
    float s = v.x + v.y + v.z + v.w;
#pragma unroll
    for (int o = 16; o; o >>= 1) s += __shfl_xor_sync(0xffffffffu, s, o);
    if (lane == 0) red[wid] = s;
    __syncthreads();
    s = red[0];
#pragma unroll
    for (int w = 1; w < 8; w++) s += red[w];

    const float inv = 1.0f / s;
    v.x *= inv; v.y *= inv; v.z *= inv; v.w *= inv;
    *reinterpret_cast<float4*>(&row[tid * 4]) = v;
}

extern "C" void kernel_launch(void* const* d_in, const int* in_sizes, int n_in,
                              void* d_out, int out_size)
{
    (void)in_sizes; (void)n_in; (void)out_size;
    const float* x  = (const float*)d_in[0];
    const float* wk = (const float*)d_in[1];
    const float* wq = (const float*)d_in[2];
    const float* wv = (const float*)d_in[3];
    float* out = (float*)d_out;

    float *vk, *vq, *vv, *kq;
    cudaGetSymbolAddress((void**)&vk, g_vk);
    cudaGetSymbolAddress((void**)&vq, g_vq);
    cudaGetSymbolAddress((void**)&vv, g_vv);
    cudaGetSymbolAddress((void**)&kq, g_kq);

    const size_t MM = (size_t)L * L;   // per-batch matrix size
    dim3 block(256);
    dim3 grid(L / BN, L / BM, BATCH);

    // Projections: vk/vq/vv[b,d,n] = sum_m x[b,m,d] * w[m,n]
    gemm_kernel<false, false><<<grid, block>>>(x, MM, wk, 0, vk, MM, 1.0f);
    gemm_kernel<false, false><<<grid, block>>>(x, MM, wq, 0, vq, MM, 1.0f);
    gemm_kernel<false, false><<<grid, block>>>(x, MM, wv, 0, vv, MM, 1.0f);

    // kq[b,d,e] = sum_n vk[b,d,n] * vq[b,e,n] / sqrt(1024)
    gemm_kernel<true, true><<<grid, block>>>(vk, MM, vq, MM, kq, MM, 1.0f / 32.0f);

    // softmax over last axis, in place
    softmax_kernel<<<BATCH * L, 256>>>(kq);

    // out[b,n,d] = sum_e vv[b,e,n] * sm[b,d,e]  (C[n][d] row-major == output layout)
    gemm_kernel<false, true><<<grid, block>>>(vv, MM, kq, MM, out, MM, 1.0f);
}

// round 3
// speedup vs baseline: 1.7207x; 1.7207x over previous
#include <cuda_runtime.h>
#include <cuda_bf16.h>
#include <cstdint>
#include <cstddef>

// ===========================================================================
// SelfAttention via mma.sync.m16n8k16 (bf16, fp32 acc), split-bf16 3-pass
// fp32 emulation. Plain-target PTX only (no tcgen05/TMA: harness emits
// compute_103 PTX which rejects 'a'-suffix features).
//   Five GEMMs: D[i][j] = sum_k A[i][k]*B[j][k], 1024^3, batch 16.
// ===========================================================================

#define L 1024
#define BATCH 16
#define PER_B ((size_t)L * L)
#define ELTS ((size_t)BATCH * L * L)

#define BM 128
#define BN 128
#define BK 32
#define STAGES 3
#define PITCH 80                       // bytes per 32-bf16 row (64B data + 16B pad)
#define COMP_B (128 * PITCH)           // one component tile (10240 B)
#define STAGE_B (4 * COMP_B)           // Ah, Al, Bh, Bl     (40960 B)
#define SMEM_DYN (STAGES * STAGE_B)    // 122880 B

// ---- scratch (device globals; cudaMalloc forbidden) ----
__device__ __align__(1024) __nv_bfloat16 g_xT_hi[ELTS], g_xT_lo[ELTS];
__device__ __align__(1024) __nv_bfloat16 g_vk_hi[ELTS], g_vk_lo[ELTS];
__device__ __align__(1024) __nv_bfloat16 g_vq_hi[ELTS], g_vq_lo[ELTS];
__device__ __align__(1024) __nv_bfloat16 g_vv_hi[ELTS], g_vv_lo[ELTS];   // vv^T
__device__ __align__(1024) __nv_bfloat16 g_sm_hi[ELTS], g_sm_lo[ELTS];
__device__ __align__(1024) __nv_bfloat16 g_w_hi[3][L * L], g_w_lo[3][L * L];
__device__ __align__(1024) float g_kq[ELTS];

// ---------------------------------------------------------------------------
__device__ __forceinline__ uint32_t smem_u32(const void* p) {
    uint32_t a;
    asm("{ .reg .u64 t; cvta.to.shared.u64 t, %1; cvt.u32.u64 %0, t; }"
        : "=r"(a) : "l"(p));
    return a;
}

__device__ __forceinline__ void cp16(uint32_t dst, const void* src) {
    asm volatile("cp.async.cg.shared.global [%0], [%1], 16;"
                 :: "r"(dst), "l"(src) : "memory");
}
#define CP_COMMIT() asm volatile("cp.async.commit_group;" ::: "memory")
#define CP_WAIT(n)  asm volatile("cp.async.wait_group %0;" :: "n"(n) : "memory")

__device__ __forceinline__ void ldsm4(uint32_t* r, uint32_t addr) {
    asm volatile("ldmatrix.sync.aligned.m8n8.x4.shared.b16 {%0,%1,%2,%3}, [%4];"
                 : "=r"(r[0]), "=r"(r[1]), "=r"(r[2]), "=r"(r[3]) : "r"(addr));
}

__device__ __forceinline__ void mma16816(float* d, const uint32_t* a,
                                         uint32_t b0, uint32_t b1) {
    asm volatile(
        "mma.sync.aligned.m16n8k16.row.col.f32.bf16.bf16.f32 "
        "{%0,%1,%2,%3}, {%4,%5,%6,%7}, {%8,%9}, {%0,%1,%2,%3};"
        : "+f"(d[0]), "+f"(d[1]), "+f"(d[2]), "+f"(d[3])
        : "r"(a[0]), "r"(a[1]), "r"(a[2]), "r"(a[3]), "r"(b0), "r"(b1));
}

// ---------------------------------------------------------------------------
// GEMM: D[i][j] = sum_k A[i][k]*B[j][k], i,j,k in [0,1024), batch via grid z.
// A,B given as hi/lo bf16 pairs, row-major k-contiguous.
// EPI==0: write fp32*scale.  EPI==1: write hi/lo bf16 split.
// ---------------------------------------------------------------------------
template <int EPI>
__global__ void __launch_bounds__(256, 1)
mma_gemm(const __nv_bfloat16* __restrict__ Ah, const __nv_bfloat16* __restrict__ Al,
         const __nv_bfloat16* __restrict__ Bh, const __nv_bfloat16* __restrict__ Bl,
         int aBatched, int bBatched, float scale,
         float* __restrict__ outF,
         __nv_bfloat16* __restrict__ outHi, __nv_bfloat16* __restrict__ outLo)
{
    extern __shared__ char dyn[];
    const uint32_t sbase = smem_u32(dyn);

    const int tid  = threadIdx.x;
    const int wid  = tid >> 5;
    const int lane = tid & 31;
    const int wm   = wid & 1;          // 2 warps along M (64 rows each)
    const int wn   = wid >> 1;         // 4 warps along N (32 cols each)

    const int M0 = blockIdx.y * BM;
    const int N0 = blockIdx.x * BN;
    const size_t zA = aBatched ? (size_t)blockIdx.z * PER_B : 0;
    const size_t zB = bBatched ? (size_t)blockIdx.z * PER_B : 0;

    // ---- cp.async assignments: comp = tid>>6 (Ah,Al,Bh,Bl), 8 chunks each ----
    const int comp = tid >> 6;
    const int t64  = tid & 63;
    const int ci   = t64 & 3;          // 16B chunk within 64B row (k-offset ci*8)
    const int r0   = t64 >> 2;         // base row, +16*i
    const __nv_bfloat16* gsrc;
    size_t gbase;
    if (comp == 0)      { gsrc = Ah; gbase = zA + (size_t)(M0 + r0) * L; }
    else if (comp == 1) { gsrc = Al; gbase = zA + (size_t)(M0 + r0) * L; }
    else if (comp == 2) { gsrc = Bh; gbase = zB + (size_t)(N0 + r0) * L; }
    else                { gsrc = Bl; gbase = zB + (size_t)(N0 + r0) * L; }
    const uint32_t sdst0 = sbase + comp * COMP_B + r0 * PITCH + ci * 16;

    // issue one stage's loads for k-tile kt
    auto load_stage = [&](int stage, int kt) {
        const uint32_t sd = sdst0 + stage * STAGE_B;
        const size_t   gk = (size_t)kt * BK + ci * 8;
#pragma unroll
        for (int i = 0; i < 8; i++)
            cp16(sd + i * (16 * PITCH), gsrc + gbase + (size_t)(i * 16) * L + gk);
    };

    // ---- prologue ----
    load_stage(0, 0); CP_COMMIT();
    load_stage(1, 1); CP_COMMIT();

    // ---- fragment addressing (loop-invariant lane parts) ----
    const uint32_t lanePart = (uint32_t)((lane & 15) * PITCH + (lane >> 4) * 16);
    const uint32_t aOffH = 0 * COMP_B + (uint32_t)(wm * 64 * PITCH) + lanePart;
    const uint32_t aOffL = 1 * COMP_B + (uint32_t)(wm * 64 * PITCH) + lanePart;
    const uint32_t bOffH = 2 * COMP_B + (uint32_t)(wn * 32 * PITCH) + lanePart;
    const uint32_t bOffL = 3 * COMP_B + (uint32_t)(wn * 32 * PITCH) + lanePart;

    float acc[4][4][4];
#pragma unroll
    for (int i = 0; i < 4; i++)
#pragma unroll
        for (int j = 0; j < 4; j++)
#pragma unroll
            for (int k = 0; k < 4; k++) acc[i][j][k] = 0.0f;

    const int NKT = L / BK;            // 32 k-tiles
    for (int kt = 0; kt < NKT; kt++) {
        CP_WAIT(1);
        __syncthreads();

        const uint32_t sb = sbase + (kt % STAGES) * STAGE_B;
#pragma unroll
        for (int ks = 0; ks < 2; ks++) {           // two k16 steps per stage
            const uint32_t ko = (uint32_t)(ks * 32);
            uint32_t ah[4][4], al[4][4];
#pragma unroll
            for (int tm = 0; tm < 4; tm++) {
                ldsm4(ah[tm], sb + aOffH + (uint32_t)(tm * 16 * PITCH) + ko);
                ldsm4(al[tm], sb + aOffL + (uint32_t)(tm * 16 * PITCH) + ko);
            }
            uint32_t bh[4][2], bl[4][2];
#pragma unroll
            for (int g = 0; g < 2; g++) {
                uint32_t t[4];
                ldsm4(t, sb + bOffH + (uint32_t)(g * 16 * PITCH) + ko);
                bh[2 * g][0] = t[0]; bh[2 * g][1] = t[2];
                bh[2 * g + 1][0] = t[1]; bh[2 * g + 1][1] = t[3];
                ldsm4(t, sb + bOffL + (uint32_t)(g * 16 * PITCH) + ko);
                bl[2 * g][0] = t[0]; bl[2 * g][1] = t[2];
                bl[2 * g + 1][0] = t[1]; bl[2 * g + 1][1] = t[3];
            }
#pragma unroll
            for (int tm = 0; tm < 4; tm++)
#pragma unroll
                for (int tn = 0; tn < 4; tn++) {
                    mma16816(acc[tm][tn], ah[tm], bh[tn][0], bh[tn][1]);
                    mma16816(acc[tm][tn], ah[tm], bl[tn][0], bl[tn][1]);
                    mma16816(acc[tm][tn], al[tm], bh[tn][0], bh[tn][1]);
                }
        }

        __syncthreads();
        if (kt + 2 < NKT) load_stage((kt + 2) % STAGES, kt + 2);
        CP_COMMIT();                    // commit (possibly empty) keeps counts sane
    }

    // ---- epilogue ----
    const int mBase = M0 + wm * 64 + (lane >> 2);
    const int cBase = N0 + wn * 32 + (lane & 3) * 2;
#pragma unroll
    for (int tm = 0; tm < 4; tm++)
#pragma unroll
        for (int tn = 0; tn < 4; tn++) {
            const float* a = acc[tm][tn];
            const int m = mBase + tm * 16;
            const int c = cBase + tn * 8;
            const size_t o0 = (size_t)blockIdx.z * PER_B + (size_t)m * L + c;
            const size_t o1 = o0 + 8 * L;
            if (EPI == 0) {
                *reinterpret_cast<float2*>(&outF[o0]) =
                    make_float2(a[0] * scale, a[1] * scale);
                *reinterpret_cast<float2*>(&outF[o1]) =
                    make_float2(a[2] * scale, a[3] * scale);
            } else {
#pragma unroll
                for (int p = 0; p < 2; p++) {
                    const float v0 = a[2 * p], v1 = a[2 * p + 1];
                    __nv_bfloat16 h0 = __float2bfloat16(v0);
                    __nv_bfloat16 h1 = __float2bfloat16(v1);
                    __nv_bfloat16 l0 = __float2bfloat16(v0 - __bfloat162float(h0));
                    __nv_bfloat16 l1 = __float2bfloat16(v1 - __bfloat162float(h1));
                    uint32_t hp = (uint32_t)__bfloat16_as_ushort(h0) |
                                  ((uint32_t)__bfloat16_as_ushort(h1) << 16);
                    uint32_t lp = (uint32_t)__bfloat16_as_ushort(l0) |
                                  ((uint32_t)__bfloat16_as_ushort(l1) << 16);
                    const size_t o = p ? o1 : o0;
                    *reinterpret_cast<uint32_t*>(&outHi[o]) = hp;
                    *reinterpret_cast<uint32_t*>(&outLo[o]) = lp;
                }
            }
        }
}

// ---------------------------------------------------------------------------
// transpose + split: fp32 [z][R][C] -> hi/lo bf16 [z][C][R]
// ---------------------------------------------------------------------------
__global__ void __launch_bounds__(256)
transpose_split(const float* __restrict__ in,
                __nv_bfloat16* __restrict__ oh, __nv_bfloat16* __restrict__ ol)
{
    __shared__ float t[32][33];
    const size_t base = (size_t)blockIdx.z * PER_B;
    const int tx = threadIdx.x, ty = threadIdx.y;
    const int r0 = blockIdx.y * 32, c0 = blockIdx.x * 32;
#pragma unroll
    for (int i = 0; i < 4; i++)
        t[ty + i * 8][tx] = in[base + (size_t)(r0 + ty + i * 8) * L + c0 + tx];
    __syncthreads();
#pragma unroll
    for (int i = 0; i < 4; i++) {
        float v = t[tx][ty + i * 8];
        __nv_bfloat16 h = __float2bfloat16(v);
        __nv_bfloat16 l = __float2bfloat16(v - __bfloat162float(h));
        size_t o = base + (size_t)(c0 + ty + i * 8) * L + r0 + tx;
        oh[o] = h;
        ol[o] = l;
    }
}

// ---------------------------------------------------------------------------
// row softmax (1024 wide) + split to hi/lo bf16
// ---------------------------------------------------------------------------
__global__ void __launch_bounds__(256)
softmax_split(const float* __restrict__ kq,
              __nv_bfloat16* __restrict__ oh, __nv_bfloat16* __restrict__ ol)
{
    const size_t rb = (size_t)blockIdx.x * L;
    const int tid = threadIdx.x;
    float4 v = *reinterpret_cast<const float4*>(&kq[rb + tid * 4]);

    __shared__ float red[8];
    const int lane = tid & 31, wid = tid >> 5;

    float m = fmaxf(fmaxf(v.x, v.y), fmaxf(v.z, v.w));
#pragma unroll
    for (int o = 16; o; o >>= 1) m = fmaxf(m, __shfl_xor_sync(0xffffffffu, m, o));
    if (lane == 0) red[wid] = m;
    __syncthreads();
    m = red[0];
#pragma unroll
    for (int w = 1; w < 8; w++) m = fmaxf(m, red[w]);
    __syncthreads();

    v.x = expf(v.x - m); v.y = expf(v.y - m);
    v.z = expf(v.z - m); v.w = expf(v.w - m);
    float s = v.x + v.y + v.z + v.w;
#pragma unroll
    for (int o = 16; o; o >>= 1) s += __shfl_xor_sync(0xffffffffu, s, o);
    if (lane == 0) red[wid] = s;
    __syncthreads();
    s = red[0];
#pragma unroll
    for (int w = 1; w < 8; w++) s += red[w];

    const float inv = 1.0f / s;
    float vals[4] = {v.x * inv, v.y * inv, v.z * inv, v.w * inv};
#pragma unroll
    for (int j = 0; j < 4; j++) {
        __nv_bfloat16 h = __float2bfloat16(vals[j]);
        __nv_bfloat16 l = __float2bfloat16(vals[j] - __bfloat162float(h));
        oh[rb + tid * 4 + j] = h;
        ol[rb + tid * 4 + j] = l;
    }
}

// ---------------------------------------------------------------------------
// host
// ---------------------------------------------------------------------------
extern "C" void kernel_launch(void* const* d_in, const int* in_sizes, int n_in,
                              void* d_out, int out_size)
{
    (void)in_sizes; (void)n_in; (void)out_size;
    const float* x = (const float*)d_in[0];
    const float* w[3] = {(const float*)d_in[1], (const float*)d_in[2],
                         (const float*)d_in[3]};
    float* out = (float*)d_out;

    void *xh, *xl, *vkh, *vkl, *vqh, *vql, *vvh, *vvl, *smh, *sml, *wh, *wl, *kq;
    cudaGetSymbolAddress(&xh, g_xT_hi);  cudaGetSymbolAddress(&xl, g_xT_lo);
    cudaGetSymbolAddress(&vkh, g_vk_hi); cudaGetSymbolAddress(&vkl, g_vk_lo);
    cudaGetSymbolAddress(&vqh, g_vq_hi); cudaGetSymbolAddress(&vql, g_vq_lo);
    cudaGetSymbolAddress(&vvh, g_vv_hi); cudaGetSymbolAddress(&vvl, g_vv_lo);
    cudaGetSymbolAddress(&smh, g_sm_hi); cudaGetSymbolAddress(&sml, g_sm_lo);
    cudaGetSymbolAddress(&wh, g_w_hi);   cudaGetSymbolAddress(&wl, g_w_lo);
    cudaGetSymbolAddress(&kq, g_kq);

    __nv_bfloat16* XH = (__nv_bfloat16*)xh;  __nv_bfloat16* XL = (__nv_bfloat16*)xl;
    __nv_bfloat16* WH = (__nv_bfloat16*)wh;  __nv_bfloat16* WL = (__nv_bfloat16*)wl;
    __nv_bfloat16* VKH = (__nv_bfloat16*)vkh; __nv_bfloat16* VKL = (__nv_bfloat16*)vkl;
    __nv_bfloat16* VQH = (__nv_bfloat16*)vqh; __nv_bfloat16* VQL = (__nv_bfloat16*)vql;
    __nv_bfloat16* VVH = (__nv_bfloat16*)vvh; __nv_bfloat16* VVL = (__nv_bfloat16*)vvl;
    __nv_bfloat16* SMH = (__nv_bfloat16*)smh; __nv_bfloat16* SML = (__nv_bfloat16*)sml;

    cudaFuncSetAttribute((const void*)mma_gemm<0>,
                         cudaFuncAttributeMaxDynamicSharedMemorySize, SMEM_DYN);
    cudaFuncSetAttribute((const void*)mma_gemm<1>,
                         cudaFuncAttributeMaxDynamicSharedMemorySize, SMEM_DYN);

    dim3 tb(32, 8);
    // xT[b,d,m] = x[b,m,d], split
    transpose_split<<<dim3(32, 32, BATCH), tb>>>(x, XH, XL);
    // wT[n,m] = w[m,n], split
    for (int i = 0; i < 3; i++)
        transpose_split<<<dim3(32, 32, 1), tb>>>(w[i], WH + (size_t)i * PER_B,
                                                 WL + (size_t)i * PER_B);

    dim3 gg(8, 8, BATCH);
    // G1: vk[d][n] = sum_m xT[d,m] * wkT[n,m]
    mma_gemm<1><<<gg, 256, SMEM_DYN>>>(XH, XL, WH, WL, 1, 0, 1.0f,
                                       nullptr, VKH, VKL);
    // G2: vq
    mma_gemm<1><<<gg, 256, SMEM_DYN>>>(XH, XL, WH + PER_B, WL + PER_B, 1, 0, 1.0f,
                                       nullptr, VQH, VQL);
    // G3: vvT[n][d] = sum_m wvT[n,m] * xT[d,m]
    mma_gemm<1><<<gg, 256, SMEM_DYN>>>(WH + 2 * PER_B, WL + 2 * PER_B, XH, XL, 0, 1,
                                       1.0f, nullptr, VVH, VVL);
    // G4: kq[d][e] = sum_n vk[d,n]*vq[e,n] / 32
    mma_gemm<0><<<gg, 256, SMEM_DYN>>>(VKH, VKL, VQH, VQL, 1, 1, 1.0f / 32.0f,
                                       (float*)kq, nullptr, nullptr);
    // softmax rows -> sm hi/lo
    softmax_split<<<BATCH * L, 256>>>((const float*)kq, SMH, SML);
    // G5: out[n][d] = sum_e vvT[n,e]*sm[d,e]
    mma_gemm<0><<<gg, 256, SMEM_DYN>>>(VVH, VVL, SMH, SML, 1, 1, 1.0f,
                                       out, nullptr, nullptr);
}

// round 4
// speedup vs baseline: 1.7390x; 1.0106x over previous
#include <cuda_runtime.h>
#include <cuda_bf16.h>
#include <cstdint>
#include <cstddef>

// ===========================================================================
// SelfAttention via mma.sync.m16n8k16 (bf16, fp32 acc), split-bf16 3-pass
// fp32 emulation. 512-thread CTAs (16 warps/SM), 32x32 warp tiles,
// pass-major MMA ordering to break accumulator RAW chains.
//   Five GEMMs: D[i][j] = sum_k A[i][k]*B[j][k], 1024^3, batch 16.
// ===========================================================================

#define L 1024
#define BATCH 16
#define PER_B ((size_t)L * L)
#define ELTS ((size_t)BATCH * L * L)

#define BM 128
#define BN 128
#define BK 32
#define STAGES 3
#define PITCH 80                        // 64B data + 16B pad per 32-bf16 row
#define COMP_B (128 * PITCH)            // 10240 B
#define STAGE_B (4 * COMP_B)            // 40960 B
#define SMEM_DYN (STAGES * STAGE_B)     // 122880 B

// ---- scratch (device globals; cudaMalloc forbidden) ----
__device__ __align__(1024) __nv_bfloat16 g_xT_hi[ELTS], g_xT_lo[ELTS];
__device__ __align__(1024) __nv_bfloat16 g_vk_hi[ELTS], g_vk_lo[ELTS];
__device__ __align__(1024) __nv_bfloat16 g_vq_hi[ELTS], g_vq_lo[ELTS];
__device__ __align__(1024) __nv_bfloat16 g_vv_hi[ELTS], g_vv_lo[ELTS];   // vv^T
__device__ __align__(1024) __nv_bfloat16 g_sm_hi[ELTS], g_sm_lo[ELTS];
__device__ __align__(1024) __nv_bfloat16 g_w_hi[3][L * L], g_w_lo[3][L * L];
__device__ __align__(1024) float g_kq[ELTS];

// ---------------------------------------------------------------------------
__device__ __forceinline__ uint32_t smem_u32(const void* p) {
    uint32_t a;
    asm("{ .reg .u64 t; cvta.to.shared.u64 t, %1; cvt.u32.u64 %0, t; }"
        : "=r"(a) : "l"(p));
    return a;
}

__device__ __forceinline__ void cp16(uint32_t dst, const void* src) {
    asm volatile("cp.async.cg.shared.global [%0], [%1], 16;"
                 :: "r"(dst), "l"(src) : "memory");
}
#define CP_COMMIT() asm volatile("cp.async.commit_group;" ::: "memory")
#define CP_WAIT(n)  asm volatile("cp.async.wait_group %0;" :: "n"(n) : "memory")

__device__ __forceinline__ void ldsm4(uint32_t* r, uint32_t addr) {
    asm volatile("ldmatrix.sync.aligned.m8n8.x4.shared.b16 {%0,%1,%2,%3}, [%4];"
                 : "=r"(r[0]), "=r"(r[1]), "=r"(r[2]), "=r"(r[3]) : "r"(addr));
}

__device__ __forceinline__ void mma16816(float* d, const uint32_t* a,
                                         uint32_t b0, uint32_t b1) {
    asm volatile(
        "mma.sync.aligned.m16n8k16.row.col.f32.bf16.bf16.f32 "
        "{%0,%1,%2,%3}, {%4,%5,%6,%7}, {%8,%9}, {%0,%1,%2,%3};"
        : "+f"(d[0]), "+f"(d[1]), "+f"(d[2]), "+f"(d[3])
        : "r"(a[0]), "r"(a[1]), "r"(a[2]), "r"(a[3]), "r"(b0), "r"(b1));
}

// ---------------------------------------------------------------------------
// Core GEMM: D[i][j] = sum_k A[i][k]*B[j][k] for one 1024x1024 problem.
// Pointers already batch-resolved. 512 threads: 4(M) x 4(N) warps, 32x32 each.
// EPI==0: fp32*scale to outF.  EPI==1: hi/lo bf16 split to outHi/outLo.
// ---------------------------------------------------------------------------
template <int EPI>
__device__ __forceinline__ void gemm_core(
    const __nv_bfloat16* __restrict__ Ah, const __nv_bfloat16* __restrict__ Al,
    const __nv_bfloat16* __restrict__ Bh, const __nv_bfloat16* __restrict__ Bl,
    float scale, float* __restrict__ outF,
    __nv_bfloat16* __restrict__ outHi, __nv_bfloat16* __restrict__ outLo)
{
    extern __shared__ char dyn[];
    const uint32_t sbase = smem_u32(dyn);

    const int tid  = threadIdx.x;
    const int wid  = tid >> 5;
    const int lane = tid & 31;
    const int wm   = wid & 3;           // 4 warps along M (32 rows each)
    const int wn   = wid >> 2;          // 4 warps along N (32 cols each)

    const int M0 = blockIdx.y * BM;
    const int N0 = blockIdx.x * BN;

    // ---- cp.async: comp = tid>>7 (Ah,Al,Bh,Bl); 128 threads per component ----
    const int comp = tid >> 7;
    const int t128 = tid & 127;
    const int ci   = t128 & 3;          // 16B chunk (k-offset ci*8)
    const int r0   = t128 >> 2;         // base row 0..31, rows r0+32*i
    const __nv_bfloat16* gsrc =
        (comp == 0) ? Ah : (comp == 1) ? Al : (comp == 2) ? Bh : Bl;
    const size_t gbase = (size_t)(((comp < 2) ? M0 : N0) + r0) * L;
    const uint32_t sdst0 = sbase + comp * COMP_B + r0 * PITCH + ci * 16;

    auto load_stage = [&](int stage, int kt) {
        const uint32_t sd = sdst0 + stage * STAGE_B;
        const size_t   gk = (size_t)kt * BK + ci * 8;
#pragma unroll
        for (int i = 0; i < 4; i++)
            cp16(sd + i * (32 * PITCH), gsrc + gbase + (size_t)(i * 32) * L + gk);
    };

    load_stage(0, 0); CP_COMMIT();
    load_stage(1, 1); CP_COMMIT();

    const uint32_t lanePart = (uint32_t)((lane & 15) * PITCH + (lane >> 4) * 16);
    const uint32_t aOffH = 0 * COMP_B + (uint32_t)(wm * 32 * PITCH) + lanePart;
    const uint32_t aOffL = 1 * COMP_B + (uint32_t)(wm * 32 * PITCH) + lanePart;
    const uint32_t bOffH = 2 * COMP_B + (uint32_t)(wn * 32 * PITCH) + lanePart;
    const uint32_t bOffL = 3 * COMP_B + (uint32_t)(wn * 32 * PITCH) + lanePart;

    float acc[2][4][4];
#pragma unroll
    for (int i = 0; i < 2; i++)
#pragma unroll
        for (int j = 0; j < 4; j++)
#pragma unroll
            for (int k = 0; k < 4; k++) acc[i][j][k] = 0.0f;

    const int NKT = L / BK;             // 32
    for (int kt = 0; kt < NKT; kt++) {
        CP_WAIT(1);
        __syncthreads();

        const uint32_t sb = sbase + (kt % STAGES) * STAGE_B;
#pragma unroll
        for (int ks = 0; ks < 2; ks++) {
            const uint32_t ko = (uint32_t)(ks * 32);
            uint32_t ah[2][4], al[2][4];
#pragma unroll
            for (int tm = 0; tm < 2; tm++) {
                ldsm4(ah[tm], sb + aOffH + (uint32_t)(tm * 16 * PITCH) + ko);
                ldsm4(al[tm], sb + aOffL + (uint32_t)(tm * 16 * PITCH) + ko);
            }
            uint32_t bh[4][2], bl[4][2];
#pragma unroll
            for (int g = 0; g < 2; g++) {
                uint32_t t[4];
                ldsm4(t, sb + bOffH + (uint32_t)(g * 16 * PITCH) + ko);
                bh[2 * g][0] = t[0];     bh[2 * g][1] = t[2];
                bh[2 * g + 1][0] = t[1]; bh[2 * g + 1][1] = t[3];
                ldsm4(t, sb + bOffL + (uint32_t)(g * 16 * PITCH) + ko);
                bl[2 * g][0] = t[0];     bl[2 * g][1] = t[2];
                bl[2 * g + 1][0] = t[1]; bl[2 * g + 1][1] = t[3];
            }
            // pass-major: 8 independent MMAs per pass, RAW distance = 8
#pragma unroll
            for (int tm = 0; tm < 2; tm++)
#pragma unroll
                for (int tn = 0; tn < 4; tn++)
                    mma16816(acc[tm][tn], ah[tm], bh[tn][0], bh[tn][1]);
#pragma unroll
            for (int tm = 0; tm < 2; tm++)
#pragma unroll
                for (int tn = 0; tn < 4; tn++)
                    mma16816(acc[tm][tn], ah[tm], bl[tn][0], bl[tn][1]);
#pragma unroll
            for (int tm = 0; tm < 2; tm++)
#pragma unroll
                for (int tn = 0; tn < 4; tn++)
                    mma16816(acc[tm][tn], al[tm], bh[tn][0], bh[tn][1]);
        }

        __syncthreads();
        if (kt + 2 < NKT) load_stage((kt + 2) % STAGES, kt + 2);
        CP_COMMIT();
    }

    // ---- epilogue ----
    const int mBase = M0 + wm * 32 + (lane >> 2);
    const int cBase = N0 + wn * 32 + (lane & 3) * 2;
#pragma unroll
    for (int tm = 0; tm < 2; tm++)
#pragma unroll
        for (int tn = 0; tn < 4; tn++) {
            const float* a = acc[tm][tn];
            const int m = mBase + tm * 16;
            const int c = cBase + tn * 8;
            const size_t o0 = (size_t)m * L + c;
            const size_t o1 = o0 + 8 * L;
            if (EPI == 0) {
                *reinterpret_cast<float2*>(&outF[o0]) =
                    make_float2(a[0] * scale, a[1] * scale);
                *reinterpret_cast<float2*>(&outF[o1]) =
                    make_float2(a[2] * scale, a[3] * scale);
            } else {
#pragma unroll
                for (int p = 0; p < 2; p++) {
                    const float v0 = a[2 * p], v1 = a[2 * p + 1];
                    __nv_bfloat16 h0 = __float2bfloat16(v0);
                    __nv_bfloat16 h1 = __float2bfloat16(v1);
                    __nv_bfloat16 l0 = __float2bfloat16(v0 - __bfloat162float(h0));
                    __nv_bfloat16 l1 = __float2bfloat16(v1 - __bfloat162float(h1));
                    uint32_t hp = (uint32_t)__bfloat16_as_ushort(h0) |
                                  ((uint32_t)__bfloat16_as_ushort(h1) << 16);
                    uint32_t lp = (uint32_t)__bfloat16_as_ushort(l0) |
                                  ((uint32_t)__bfloat16_as_ushort(l1) << 16);
                    const size_t o = p ? o1 : o0;
                    *reinterpret_cast<uint32_t*>(&outHi[o]) = hp;
                    *reinterpret_cast<uint32_t*>(&outLo[o]) = lp;
                }
            }
        }
}

// ---------------------------------------------------------------------------
// Fused projections: z = proj*16 + batch.  proj 0: vk = xT@wk^T,
// proj 1: vq, proj 2: vv^T = wvT @ xT^T.  All EPI=1 (hi/lo split out).
// ---------------------------------------------------------------------------
__global__ void __launch_bounds__(512, 1)
proj_kernel(const __nv_bfloat16* __restrict__ XH, const __nv_bfloat16* __restrict__ XL,
            const __nv_bfloat16* __restrict__ WH, const __nv_bfloat16* __restrict__ WL,
            __nv_bfloat16* __restrict__ VKH, __nv_bfloat16* __restrict__ VKL,
            __nv_bfloat16* __restrict__ VQH, __nv_bfloat16* __restrict__ VQL,
            __nv_bfloat16* __restrict__ VVH, __nv_bfloat16* __restrict__ VVL)
{
    const int z = blockIdx.z;
    const int proj = z >> 4;
    const size_t bo = (size_t)(z & 15) * PER_B;

    const __nv_bfloat16 *Ah, *Al, *Bh, *Bl;
    __nv_bfloat16 *oh, *ol;
    if (proj == 0) {
        Ah = XH + bo; Al = XL + bo; Bh = WH; Bl = WL;
        oh = VKH + bo; ol = VKL + bo;
    } else if (proj == 1) {
        Ah = XH + bo; Al = XL + bo; Bh = WH + PER_B; Bl = WL + PER_B;
        oh = VQH + bo; ol = VQL + bo;
    } else {
        Ah = WH + 2 * PER_B; Al = WL + 2 * PER_B; Bh = XH + bo; Bl = XL + bo;
        oh = VVH + bo; ol = VVL + bo;
    }
    gemm_core<1>(Ah, Al, Bh, Bl, 1.0f, nullptr, oh, ol);
}

// Batched GEMM, fp32 output: used for kq and final out.
__global__ void __launch_bounds__(512, 1)
gemm_f32(const __nv_bfloat16* __restrict__ Ah, const __nv_bfloat16* __restrict__ Al,
         const __nv_bfloat16* __restrict__ Bh, const __nv_bfloat16* __restrict__ Bl,
         float scale, float* __restrict__ outF)
{
    const size_t bo = (size_t)blockIdx.z * PER_B;
    gemm_core<0>(Ah + bo, Al + bo, Bh + bo, Bl + bo, scale, outF + bo,
                 nullptr, nullptr);
}

// ---------------------------------------------------------------------------
// Fused transpose + split: z<16 -> x batch z; z=16..18 -> w[z-16].
// fp32 [R][C] -> hi/lo bf16 [C][R]
// ---------------------------------------------------------------------------
__global__ void __launch_bounds__(256)
transpose_split(const float* __restrict__ x,
                const float* __restrict__ w0, const float* __restrict__ w1,
                const float* __restrict__ w2,
                __nv_bfloat16* __restrict__ XH, __nv_bfloat16* __restrict__ XL,
                __nv_bfloat16* __restrict__ WH, __nv_bfloat16* __restrict__ WL)
{
    __shared__ float t[32][33];
    const int z = blockIdx.z;
    const float* in;
    __nv_bfloat16 *oh, *ol;
    if (z < 16) {
        in = x + (size_t)z * PER_B;
        oh = XH + (size_t)z * PER_B; ol = XL + (size_t)z * PER_B;
    } else {
        in = (z == 16) ? w0 : (z == 17) ? w1 : w2;
        oh = WH + (size_t)(z - 16) * PER_B; ol = WL + (size_t)(z - 16) * PER_B;
    }
    const int tx = threadIdx.x, ty = threadIdx.y;
    const int r0 = blockIdx.y * 32, c0 = blockIdx.x * 32;
#pragma unroll
    for (int i = 0; i < 4; i++)
        t[ty + i * 8][tx] = in[(size_t)(r0 + ty + i * 8) * L + c0 + tx];
    __syncthreads();
#pragma unroll
    for (int i = 0; i < 4; i++) {
        float v = t[tx][ty + i * 8];
        __nv_bfloat16 h = __float2bfloat16(v);
        __nv_bfloat16 l = __float2bfloat16(v - __bfloat162float(h));
        size_t o = (size_t)(c0 + ty + i * 8) * L + r0 + tx;
        oh[o] = h;
        ol[o] = l;
    }
}

// ---------------------------------------------------------------------------
// row softmax (1024 wide) + split to hi/lo bf16
// ---------------------------------------------------------------------------
__global__ void __launch_bounds__(256)
softmax_split(const float* __restrict__ kq,
              __nv_bfloat16* __restrict__ oh, __nv_bfloat16* __restrict__ ol)
{
    const size_t rb = (size_t)blockIdx.x * L;
    const int tid = threadIdx.x;
    float4 v = *reinterpret_cast<const float4*>(&kq[rb + tid * 4]);

    __shared__ float red[8];
    const int lane = tid & 31, wid = tid >> 5;

    float m = fmaxf(fmaxf(v.x, v.y), fmaxf(v.z, v.w));
#pragma unroll
    for (int o = 16; o; o >>= 1) m = fmaxf(m, __shfl_xor_sync(0xffffffffu, m, o));
    if (lane == 0) red[wid] = m;
    __syncthreads();
    m = red[0];
#pragma unroll
    for (int w = 1; w < 8; w++) m = fmaxf(m, red[w]);
    __syncthreads();

    v.x = expf(v.x - m); v.y = expf(v.y - m);
    v.z = expf(v.z - m); v.w = expf(v.w - m);
    float s = v.x + v.y + v.z + v.w;
#pragma unroll
    for (int o = 16; o; o >>= 1) s += __shfl_xor_sync(0xffffffffu, s, o);
    if (lane == 0) red[wid] = s;
    __syncthreads();
    s = red[0];
#pragma unroll
    for (int w = 1; w < 8; w++) s += red[w];

    const float inv = 1.0f / s;
    float vals[4] = {v.x * inv, v.y * inv, v.z * inv, v.w * inv};
#pragma unroll
    for (int j = 0; j < 4; j++) {
        __nv_bfloat16 h = __float2bfloat16(vals[j]);
        __nv_bfloat16 l = __float2bfloat16(vals[j] - __bfloat162float(h));
        oh[rb + tid * 4 + j] = h;
        ol[rb + tid * 4 + j] = l;
    }
}

// ---------------------------------------------------------------------------
// host
// ---------------------------------------------------------------------------
extern "C" void kernel_launch(void* const* d_in, const int* in_sizes, int n_in,
                              void* d_out, int out_size)
{
    (void)in_sizes; (void)n_in; (void)out_size;
    const float* x  = (const float*)d_in[0];
    const float* w0 = (const float*)d_in[1];
    const float* w1 = (const float*)d_in[2];
    const float* w2 = (const float*)d_in[3];
    float* out = (float*)d_out;

    void *xh, *xl, *vkh, *vkl, *vqh, *vql, *vvh, *vvl, *smh, *sml, *wh, *wl, *kq;
    cudaGetSymbolAddress(&xh, g_xT_hi);  cudaGetSymbolAddress(&xl, g_xT_lo);
    cudaGetSymbolAddress(&vkh, g_vk_hi); cudaGetSymbolAddress(&vkl, g_vk_lo);
    cudaGetSymbolAddress(&vqh, g_vq_hi); cudaGetSymbolAddress(&vql, g_vq_lo);
    cudaGetSymbolAddress(&vvh, g_vv_hi); cudaGetSymbolAddress(&vvl, g_vv_lo);
    cudaGetSymbolAddress(&smh, g_sm_hi); cudaGetSymbolAddress(&sml, g_sm_lo);
    cudaGetSymbolAddress(&wh, g_w_hi);   cudaGetSymbolAddress(&wl, g_w_lo);
    cudaGetSymbolAddress(&kq, g_kq);

    __nv_bfloat16* XH = (__nv_bfloat16*)xh;   __nv_bfloat16* XL = (__nv_bfloat16*)xl;
    __nv_bfloat16* WH = (__nv_bfloat16*)wh;   __nv_bfloat16* WL = (__nv_bfloat16*)wl;
    __nv_bfloat16* VKH = (__nv_bfloat16*)vkh; __nv_bfloat16* VKL = (__nv_bfloat16*)vkl;
    __nv_bfloat16* VQH = (__nv_bfloat16*)vqh; __nv_bfloat16* VQL = (__nv_bfloat16*)vql;
    __nv_bfloat16* VVH = (__nv_bfloat16*)vvh; __nv_bfloat16* VVL = (__nv_bfloat16*)vvl;
    __nv_bfloat16* SMH = (__nv_bfloat16*)smh; __nv_bfloat16* SML = (__nv_bfloat16*)sml;

    cudaFuncSetAttribute((const void*)proj_kernel,
                         cudaFuncAttributeMaxDynamicSharedMemorySize, SMEM_DYN);
    cudaFuncSetAttribute((const void*)gemm_f32,
                         cudaFuncAttributeMaxDynamicSharedMemorySize, SMEM_DYN);

    // fused transpose+split: x (16 batches) + 3 weights
    transpose_split<<<dim3(32, 32, 19), dim3(32, 8)>>>(x, w0, w1, w2,
                                                       XH, XL, WH, WL);
    // fused projections (48 problem instances)
    proj_kernel<<<dim3(8, 8, 48), 512, SMEM_DYN>>>(XH, XL, WH, WL,
                                                   VKH, VKL, VQH, VQL, VVH, VVL);
    // kq[d][e] = sum_n vk[d,n]*vq[e,n] / 32
    gemm_f32<<<dim3(8, 8, BATCH), 512, SMEM_DYN>>>(VKH, VKL, VQH, VQL,
                                                   1.0f / 32.0f, (float*)kq);
    // softmax rows -> sm hi/lo
    softmax_split<<<BATCH * L, 256>>>((const float*)kq, SMH, SML);
    // out[n][d] = sum_e vvT[n,e]*sm[d,e]
    gemm_f32<<<dim3(8, 8, BATCH), 512, SMEM_DYN>>>(VVH, VVL, SMH, SML,
                                                   1.0f, out);
}

// round 5
// speedup vs baseline: 1.9784x; 1.1377x over previous
#include <cuda_runtime.h>
#include <cuda_fp16.h>
#include <cstdint>
#include <cstddef>

// ===========================================================================
// SelfAttention via mma.sync.m16n8k16 (fp16 digits, fp32 acc), split-fp16
// multi-pass fp32 emulation. Logits path (G1,G2,G4): 3-pass. Output path
// (G3,G5): 2-pass (one operand single-digit fp16, err ~2.4e-4 within budget).
//   Five GEMMs: D[i][j] = sum_k A[i][k]*B[j][k], 1024^3, batch 16.
// ===========================================================================

#define L 1024
#define BATCH 16
#define PER_B ((size_t)L * L)
#define ELTS ((size_t)BATCH * L * L)

#define BM 128
#define BN 128
#define BK 32
#define STAGES 3
#define PITCH 80                        // 64B data + 16B pad per 32-fp16 row
#define COMP_B (128 * PITCH)            // 10240 B
#define STAGE_B (4 * COMP_B)            // 40960 B
#define SMEM_DYN (STAGES * STAGE_B)     // 122880 B

#define W_PRESCALE 256.0f               // keep w_lo out of fp16 subnormals
#define W_UNSCALE (1.0f / 256.0f)

// ---- scratch (device globals; cudaMalloc forbidden) ----
__device__ __align__(1024) __half g_xT_hi[ELTS], g_xT_lo[ELTS];
__device__ __align__(1024) __half g_vk_hi[ELTS], g_vk_lo[ELTS];
__device__ __align__(1024) __half g_vq_hi[ELTS], g_vq_lo[ELTS];
__device__ __align__(1024) __half g_vv_hi[ELTS], g_vv_lo[ELTS];   // vv^T
__device__ __align__(1024) __half g_sm_hi[ELTS];                  // sm: hi only
__device__ __align__(1024) __half g_w_hi[3][L * L], g_w_lo[3][L * L];
__device__ __align__(1024) float g_kq[ELTS];

// ---------------------------------------------------------------------------
__device__ __forceinline__ uint32_t smem_u32(const void* p) {
    uint32_t a;
    asm("{ .reg .u64 t; cvta.to.shared.u64 t, %1; cvt.u32.u64 %0, t; }"
        : "=r"(a) : "l"(p));
    return a;
}

__device__ __forceinline__ void cp16(uint32_t dst, const void* src) {
    asm volatile("cp.async.cg.shared.global [%0], [%1], 16;"
                 :: "r"(dst), "l"(src) : "memory");
}
#define CP_COMMIT() asm volatile("cp.async.commit_group;" ::: "memory")
#define CP_WAIT(n)  asm volatile("cp.async.wait_group %0;" :: "n"(n) : "memory")

__device__ __forceinline__ void ldsm4(uint32_t* r, uint32_t addr) {
    asm volatile("ldmatrix.sync.aligned.m8n8.x4.shared.b16 {%0,%1,%2,%3}, [%4];"
                 : "=r"(r[0]), "=r"(r[1]), "=r"(r[2]), "=r"(r[3]) : "r"(addr));
}

__device__ __forceinline__ void mma16816(float* d, const uint32_t* a,
                                         uint32_t b0, uint32_t b1) {
    asm volatile(
        "mma.sync.aligned.m16n8k16.row.col.f32.f16.f16.f32 "
        "{%0,%1,%2,%3}, {%4,%5,%6,%7}, {%8,%9}, {%0,%1,%2,%3};"
        : "+f"(d[0]), "+f"(d[1]), "+f"(d[2]), "+f"(d[3])
        : "r"(a[0]), "r"(a[1]), "r"(a[2]), "r"(a[3]), "r"(b0), "r"(b1));
}

// ---------------------------------------------------------------------------
// Core GEMM: D[i][j] = sum_k A[i][k]*B[j][k] for one 1024x1024 problem.
// 512 threads: 4(M) x 4(N) warps, 32x32 warp tiles.
// Passes: Ah*Bh always; Ah*Bl if USE_BL; Al*Bh if USE_AL.
// EPI==0: fp32*scale to outF.  EPI==1: hi/lo fp16 split (of acc*scale).
// ---------------------------------------------------------------------------
template <int EPI, bool USE_AL, bool USE_BL>
__device__ __forceinline__ void gemm_core(
    const __half* __restrict__ Ah, const __half* __restrict__ Al,
    const __half* __restrict__ Bh, const __half* __restrict__ Bl,
    float scale, float* __restrict__ outF,
    __half* __restrict__ outHi, __half* __restrict__ outLo)
{
    extern __shared__ char dyn[];
    const uint32_t sbase = smem_u32(dyn);

    const int tid  = threadIdx.x;
    const int wid  = tid >> 5;
    const int lane = tid & 31;
    const int wm   = wid & 3;           // 4 warps along M (32 rows each)
    const int wn   = wid >> 2;          // 4 warps along N (32 cols each)

    const int M0 = blockIdx.y * BM;
    const int N0 = blockIdx.x * BN;

    // ---- cp.async: comp = tid>>7 (Ah,Al,Bh,Bl); 128 threads per component ----
    const int comp = tid >> 7;
    const int t128 = tid & 127;
    const int ci   = t128 & 3;          // 16B chunk (k-offset ci*8)
    const int r0   = t128 >> 2;         // base row 0..31, rows r0+32*i
    const __half* gsrc =
        (comp == 0) ? Ah : (comp == 1) ? Al : (comp == 2) ? Bh : Bl;
    const size_t gbase = (size_t)(((comp < 2) ? M0 : N0) + r0) * L;
    const uint32_t sdst0 = sbase + comp * COMP_B + r0 * PITCH + ci * 16;
    const bool doLoad = !((comp == 1 && !USE_AL) || (comp == 3 && !USE_BL));

    auto load_stage = [&](int stage, int kt) {
        if (!doLoad) return;
        const uint32_t sd = sdst0 + stage * STAGE_B;
        const size_t   gk = (size_t)kt * BK + ci * 8;
#pragma unroll
        for (int i = 0; i < 4; i++)
            cp16(sd + i * (32 * PITCH), gsrc + gbase + (size_t)(i * 32) * L + gk);
    };

    load_stage(0, 0); CP_COMMIT();
    load_stage(1, 1); CP_COMMIT();

    const uint32_t lanePart = (uint32_t)((lane & 15) * PITCH + (lane >> 4) * 16);
    const uint32_t aOffH = 0 * COMP_B + (uint32_t)(wm * 32 * PITCH) + lanePart;
    const uint32_t aOffL = 1 * COMP_B + (uint32_t)(wm * 32 * PITCH) + lanePart;
    const uint32_t bOffH = 2 * COMP_B + (uint32_t)(wn * 32 * PITCH) + lanePart;
    const uint32_t bOffL = 3 * COMP_B + (uint32_t)(wn * 32 * PITCH) + lanePart;

    float acc[2][4][4];
#pragma unroll
    for (int i = 0; i < 2; i++)
#pragma unroll
        for (int j = 0; j < 4; j++)
#pragma unroll
            for (int k = 0; k < 4; k++) acc[i][j][k] = 0.0f;

    const int NKT = L / BK;             // 32
    for (int kt = 0; kt < NKT; kt++) {
        CP_WAIT(1);
        __syncthreads();

        const uint32_t sb = sbase + (kt % STAGES) * STAGE_B;
#pragma unroll
        for (int ks = 0; ks < 2; ks++) {
            const uint32_t ko = (uint32_t)(ks * 32);
            uint32_t ah[2][4], al[2][4];
#pragma unroll
            for (int tm = 0; tm < 2; tm++) {
                ldsm4(ah[tm], sb + aOffH + (uint32_t)(tm * 16 * PITCH) + ko);
                if (USE_AL)
                    ldsm4(al[tm], sb + aOffL + (uint32_t)(tm * 16 * PITCH) + ko);
            }
            uint32_t bh[4][2], bl[4][2];
#pragma unroll
            for (int g = 0; g < 2; g++) {
                uint32_t t[4];
                ldsm4(t, sb + bOffH + (uint32_t)(g * 16 * PITCH) + ko);
                bh[2 * g][0] = t[0];     bh[2 * g][1] = t[2];
                bh[2 * g + 1][0] = t[1]; bh[2 * g + 1][1] = t[3];
                if (USE_BL) {
                    ldsm4(t, sb + bOffL + (uint32_t)(g * 16 * PITCH) + ko);
                    bl[2 * g][0] = t[0];     bl[2 * g][1] = t[2];
                    bl[2 * g + 1][0] = t[1]; bl[2 * g + 1][1] = t[3];
                }
            }
            // pass-major: independent MMAs within each pass
#pragma unroll
            for (int tm = 0; tm < 2; tm++)
#pragma unroll
                for (int tn = 0; tn < 4; tn++)
                    mma16816(acc[tm][tn], ah[tm], bh[tn][0], bh[tn][1]);
            if (USE_BL) {
#pragma unroll
                for (int tm = 0; tm < 2; tm++)
#pragma unroll
                    for (int tn = 0; tn < 4; tn++)
                        mma16816(acc[tm][tn], ah[tm], bl[tn][0], bl[tn][1]);
            }
            if (USE_AL) {
#pragma unroll
                for (int tm = 0; tm < 2; tm++)
#pragma unroll
                    for (int tn = 0; tn < 4; tn++)
                        mma16816(acc[tm][tn], al[tm], bh[tn][0], bh[tn][1]);
            }
        }

        __syncthreads();
        if (kt + 2 < NKT) load_stage((kt + 2) % STAGES, kt + 2);
        CP_COMMIT();
    }

    // ---- epilogue ----
    const int mBase = M0 + wm * 32 + (lane >> 2);
    const int cBase = N0 + wn * 32 + (lane & 3) * 2;
#pragma unroll
    for (int tm = 0; tm < 2; tm++)
#pragma unroll
        for (int tn = 0; tn < 4; tn++) {
            const float* a = acc[tm][tn];
            const int m = mBase + tm * 16;
            const int c = cBase + tn * 8;
            const size_t o0 = (size_t)m * L + c;
            const size_t o1 = o0 + 8 * L;
            if (EPI == 0) {
                *reinterpret_cast<float2*>(&outF[o0]) =
                    make_float2(a[0] * scale, a[1] * scale);
                *reinterpret_cast<float2*>(&outF[o1]) =
                    make_float2(a[2] * scale, a[3] * scale);
            } else {
#pragma unroll
                for (int p = 0; p < 2; p++) {
                    const float v0 = a[2 * p] * scale, v1 = a[2 * p + 1] * scale;
                    __half h0 = __float2half(v0);
                    __half h1 = __float2half(v1);
                    __half l0 = __float2half(v0 - __half2float(h0));
                    __half l1 = __float2half(v1 - __half2float(h1));
                    uint32_t hp = (uint32_t)__half_as_ushort(h0) |
                                  ((uint32_t)__half_as_ushort(h1) << 16);
                    uint32_t lp = (uint32_t)__half_as_ushort(l0) |
                                  ((uint32_t)__half_as_ushort(l1) << 16);
                    const size_t o = p ? o1 : o0;
                    *reinterpret_cast<uint32_t*>(&outHi[o]) = hp;
                    *reinterpret_cast<uint32_t*>(&outLo[o]) = lp;
                }
            }
        }
}

// ---------------------------------------------------------------------------
// Fused projections: z = proj*16 + batch.
//   proj 0: vk = xT @ wk^T      (3-pass, x 2-digit, w 2-digit)
//   proj 1: vq                   (3-pass)
//   proj 2: vv^T = wvT @ xT^T    (2-pass: wv single-digit, x 2-digit)
// w was prescaled by 256 -> epilogue scale 1/256.
// ---------------------------------------------------------------------------
__global__ void __launch_bounds__(512, 1)
proj_kernel(const __half* __restrict__ XH, const __half* __restrict__ XL,
            const __half* __restrict__ WH, const __half* __restrict__ WL,
            __half* __restrict__ VKH, __half* __restrict__ VKL,
            __half* __restrict__ VQH, __half* __restrict__ VQL,
            __half* __restrict__ VVH, __half* __restrict__ VVL)
{
    const int z = blockIdx.z;
    const int proj = z >> 4;
    const size_t bo = (size_t)(z & 15) * PER_B;

    if (proj == 0) {
        gemm_core<1, true, true>(XH + bo, XL + bo, WH, WL, W_UNSCALE,
                                 nullptr, VKH + bo, VKL + bo);
    } else if (proj == 1) {
        gemm_core<1, true, true>(XH + bo, XL + bo, WH + PER_B, WL + PER_B,
                                 W_UNSCALE, nullptr, VQH + bo, VQL + bo);
    } else {
        // A = wv (single digit), B = xT (2-digit): passes hh + h*bl
        gemm_core<1, false, true>(WH + 2 * PER_B, WL + 2 * PER_B, XH + bo, XL + bo,
                                  W_UNSCALE, nullptr, VVH + bo, VVL + bo);
    }
}

// G4: kq = vk . vq / 32, full 3-pass, fp32 out.
__global__ void __launch_bounds__(512, 1)
kq_kernel(const __half* __restrict__ Ah, const __half* __restrict__ Al,
          const __half* __restrict__ Bh, const __half* __restrict__ Bl,
          float* __restrict__ outF)
{
    const size_t bo = (size_t)blockIdx.z * PER_B;
    gemm_core<0, true, true>(Ah + bo, Al + bo, Bh + bo, Bl + bo,
                             1.0f / 32.0f, outF + bo, nullptr, nullptr);
}

// G5: out = vv^T . sm, 2-pass (vv 2-digit, sm single-digit), fp32 out.
__global__ void __launch_bounds__(512, 1)
out_kernel(const __half* __restrict__ Ah, const __half* __restrict__ Al,
           const __half* __restrict__ Bh,
           float* __restrict__ outF)
{
    const size_t bo = (size_t)blockIdx.z * PER_B;
    gemm_core<0, true, false>(Ah + bo, Al + bo, Bh + bo, nullptr,
                              1.0f, outF + bo, nullptr, nullptr);
}

// ---------------------------------------------------------------------------
// Fused transpose + split: z<16 -> x batch z (prescale 1); z=16..18 -> w[z-16]
// (prescale 256).  fp32 [R][C] -> hi/lo fp16 [C][R]
// ---------------------------------------------------------------------------
__global__ void __launch_bounds__(256)
transpose_split(const float* __restrict__ x,
                const float* __restrict__ w0, const float* __restrict__ w1,
                const float* __restrict__ w2,
                __half* __restrict__ XH, __half* __restrict__ XL,
                __half* __restrict__ WH, __half* __restrict__ WL)
{
    __shared__ float t[32][33];
    const int z = blockIdx.z;
    const float* in;
    __half *oh, *ol;
    float pres;
    if (z < 16) {
        in = x + (size_t)z * PER_B;
        oh = XH + (size_t)z * PER_B; ol = XL + (size_t)z * PER_B;
        pres = 1.0f;
    } else {
        in = (z == 16) ? w0 : (z == 17) ? w1 : w2;
        oh = WH + (size_t)(z - 16) * PER_B; ol = WL + (size_t)(z - 16) * PER_B;
        pres = W_PRESCALE;
    }
    const int tx = threadIdx.x, ty = threadIdx.y;
    const int r0 = blockIdx.y * 32, c0 = blockIdx.x * 32;
#pragma unroll
    for (int i = 0; i < 4; i++)
        t[ty + i * 8][tx] = in[(size_t)(r0 + ty + i * 8) * L + c0 + tx];
    __syncthreads();
#pragma unroll
    for (int i = 0; i < 4; i++) {
        float v = t[tx][ty + i * 8] * pres;
        __half h = __float2half(v);
        __half l = __float2half(v - __half2float(h));
        size_t o = (size_t)(c0 + ty + i * 8) * L + r0 + tx;
        oh[o] = h;
        ol[o] = l;
    }
}

// ---------------------------------------------------------------------------
// row softmax (1024 wide), output single-digit fp16
// ---------------------------------------------------------------------------
__global__ void __launch_bounds__(256)
softmax_h(const float* __restrict__ kq, __half* __restrict__ oh)
{
    const size_t rb = (size_t)blockIdx.x * L;
    const int tid = threadIdx.x;
    float4 v = *reinterpret_cast<const float4*>(&kq[rb + tid * 4]);

    __shared__ float red[8];
    const int lane = tid & 31, wid = tid >> 5;

    float m = fmaxf(fmaxf(v.x, v.y), fmaxf(v.z, v.w));
#pragma unroll
    for (int o = 16; o; o >>= 1) m = fmaxf(m, __shfl_xor_sync(0xffffffffu, m, o));
    if (lane == 0) red[wid] = m;
    __syncthreads();
    m = red[0];
#pragma unroll
    for (int w = 1; w < 8; w++) m = fmaxf(m, red[w]);
    __syncthreads();

    v.x = expf(v.x - m); v.y = expf(v.y - m);
    v.z = expf(v.z - m); v.w = expf(v.w - m);
    float s = v.x + v.y + v.z + v.w;
#pragma unroll
    for (int o = 16; o; o >>= 1) s += __shfl_xor_sync(0xffffffffu, s, o);
    if (lane == 0) red[wid] = s;
    __syncthreads();
    s = red[0];
#pragma unroll
    for (int w = 1; w < 8; w++) s += red[w];

    const float inv = 1.0f / s;
    uint32_t p0 = (uint32_t)__half_as_ushort(__float2half(v.x * inv)) |
                  ((uint32_t)__half_as_ushort(__float2half(v.y * inv)) << 16);
    uint32_t p1 = (uint32_t)__half_as_ushort(__float2half(v.z * inv)) |
                  ((uint32_t)__half_as_ushort(__float2half(v.w * inv)) << 16);
    *reinterpret_cast<uint2*>(&oh[rb + tid * 4]) = make_uint2(p0, p1);
}

// ---------------------------------------------------------------------------
// host
// ---------------------------------------------------------------------------
extern "C" void kernel_launch(void* const* d_in, const int* in_sizes, int n_in,
                              void* d_out, int out_size)
{
    (void)in_sizes; (void)n_in; (void)out_size;
    const float* x  = (const float*)d_in[0];
    const float* w0 = (const float*)d_in[1];
    const float* w1 = (const float*)d_in[2];
    const float* w2 = (const float*)d_in[3];
    float* out = (float*)d_out;

    void *xh, *xl, *vkh, *vkl, *vqh, *vql, *vvh, *vvl, *smh, *wh, *wl, *kq;
    cudaGetSymbolAddress(&xh, g_xT_hi);  cudaGetSymbolAddress(&xl, g_xT_lo);
    cudaGetSymbolAddress(&vkh, g_vk_hi); cudaGetSymbolAddress(&vkl, g_vk_lo);
    cudaGetSymbolAddress(&vqh, g_vq_hi); cudaGetSymbolAddress(&vql, g_vq_lo);
    cudaGetSymbolAddress(&vvh, g_vv_hi); cudaGetSymbolAddress(&vvl, g_vv_lo);
    cudaGetSymbolAddress(&smh, g_sm_hi);
    cudaGetSymbolAddress(&wh, g_w_hi);   cudaGetSymbolAddress(&wl, g_w_lo);
    cudaGetSymbolAddress(&kq, g_kq);

    __half* XH = (__half*)xh;   __half* XL = (__half*)xl;
    __half* WH = (__half*)wh;   __half* WL = (__half*)wl;
    __half* VKH = (__half*)vkh; __half* VKL = (__half*)vkl;
    __half* VQH = (__half*)vqh; __half* VQL = (__half*)vql;
    __half* VVH = (__half*)vvh; __half* VVL = (__half*)vvl;
    __half* SMH = (__half*)smh;

    cudaFuncSetAttribute((const void*)proj_kernel,
                         cudaFuncAttributeMaxDynamicSharedMemorySize, SMEM_DYN);
    cudaFuncSetAttribute((const void*)kq_kernel,
                         cudaFuncAttributeMaxDynamicSharedMemorySize, SMEM_DYN);
    cudaFuncSetAttribute((const void*)out_kernel,
                         cudaFuncAttributeMaxDynamicSharedMemorySize, SMEM_DYN);

    // fused transpose+split: x (16 batches, pres 1) + 3 weights (pres 256)
    transpose_split<<<dim3(32, 32, 19), dim3(32, 8)>>>(x, w0, w1, w2,
                                                       XH, XL, WH, WL);
    // fused projections (48 instances: vk, vq 3-pass; vv 2-pass)
    proj_kernel<<<dim3(8, 8, 48), 512, SMEM_DYN>>>(XH, XL, WH, WL,
                                                   VKH, VKL, VQH, VQL, VVH, VVL);
    // kq[d][e] = sum_n vk[d,n]*vq[e,n] / 32   (3-pass)
    kq_kernel<<<dim3(8, 8, BATCH), 512, SMEM_DYN>>>(VKH, VKL, VQH, VQL,
                                                    (float*)kq);
    // softmax rows -> sm hi (single digit)
    softmax_h<<<BATCH * L, 256>>>((const float*)kq, SMH);
    // out[n][d] = sum_e vvT[n,e]*sm[d,e]   (2-pass)
    out_kernel<<<dim3(8, 8, BATCH), 512, SMEM_DYN>>>(VVH, VVL, SMH, out);
}

// round 6
// speedup vs baseline: 2.3970x; 1.2116x over previous
#include <cuda_runtime.h>
#include <cuda_fp16.h>
#include <cstdint>
#include <cstddef>

// ===========================================================================
// SelfAttention via mma.sync.m16n8k16 (fp16 digits, fp32 acc), split-fp16
// multi-pass fp32 emulation + algebraic restructuring:
//   G  = wk . wq^T                (unbatched, 3-pass)      ~3/16 unit
//   tT = xT . G                   (batched,   3-pass)       3 units
//   kq = xT . tT / 32             (batched,   3-pass)       3 units
//   sm = softmax(kq)              (1-digit fp16 out)
//   u  = sm . x_natural           (batched,   2-pass)       2 units
//   out= wvT . u                  (batched,   2-pass)       2 units
// vs previous 13 units -> 10.2 units.
// ===========================================================================

#define L 1024
#define BATCH 16
#define PER_B ((size_t)L * L)
#define ELTS ((size_t)BATCH * L * L)

#define BM 128
#define BN 128
#define BK 32
#define STAGES 3
#define PITCH 80                        // 64B data + 16B pad per 32-fp16 row
#define COMP_B (128 * PITCH)            // 10240 B
#define STAGE_B (4 * COMP_B)            // 40960 B
#define SMEM_DYN (STAGES * STAGE_B)     // 122880 B

#define W_PRESCALE 256.0f

// ---- scratch (device globals; cudaMalloc forbidden) ----
__device__ __align__(1024) __half g_xT_hi[ELTS], g_xT_lo[ELTS];   // x transposed
__device__ __align__(1024) __half g_xN_hi[ELTS], g_xN_lo[ELTS];   // x natural
__device__ __align__(1024) __half g_tT_hi[ELTS], g_tT_lo[ELTS];   // (G.x)^T * 16
__device__ __align__(1024) __half g_sm_hi[ELTS];                  // softmax, 1 digit
__device__ __align__(1024) __half g_u_hi[ELTS],  g_u_lo[ELTS];    // (sm.x^T) * 256
__device__ __align__(1024) __half g_G_hi[L * L], g_G_lo[L * L];   // wk.wq^T * 16
__device__ __align__(1024) __half g_wkN_hi[L * L], g_wkN_lo[L * L];  // *256
__device__ __align__(1024) __half g_wqN_hi[L * L], g_wqN_lo[L * L];  // *256
__device__ __align__(1024) __half g_wvT_hi[L * L], g_wvT_lo[L * L];  // *256
__device__ __align__(1024) float g_kq[ELTS];

// ---------------------------------------------------------------------------
__device__ __forceinline__ uint32_t smem_u32(const void* p) {
    uint32_t a;
    asm("{ .reg .u64 t; cvta.to.shared.u64 t, %1; cvt.u32.u64 %0, t; }"
        : "=r"(a) : "l"(p));
    return a;
}

__device__ __forceinline__ void cp16(uint32_t dst, const void* src) {
    asm volatile("cp.async.cg.shared.global [%0], [%1], 16;"
                 :: "r"(dst), "l"(src) : "memory");
}
#define CP_COMMIT() asm volatile("cp.async.commit_group;" ::: "memory")
#define CP_WAIT(n)  asm volatile("cp.async.wait_group %0;" :: "n"(n) : "memory")

__device__ __forceinline__ void ldsm4(uint32_t* r, uint32_t addr) {
    asm volatile("ldmatrix.sync.aligned.m8n8.x4.shared.b16 {%0,%1,%2,%3}, [%4];"
                 : "=r"(r[0]), "=r"(r[1]), "=r"(r[2]), "=r"(r[3]) : "r"(addr));
}

__device__ __forceinline__ void mma16816(float* d, const uint32_t* a,
                                         uint32_t b0, uint32_t b1) {
    asm volatile(
        "mma.sync.aligned.m16n8k16.row.col.f32.f16.f16.f32 "
        "{%0,%1,%2,%3}, {%4,%5,%6,%7}, {%8,%9}, {%0,%1,%2,%3};"
        : "+f"(d[0]), "+f"(d[1]), "+f"(d[2]), "+f"(d[3])
        : "r"(a[0]), "r"(a[1]), "r"(a[2]), "r"(a[3]), "r"(b0), "r"(b1));
}

// ---------------------------------------------------------------------------
// Core GEMM: D[i][j] = sum_k A[i][k]*B[j][k] for one 1024x1024 problem.
// 512 threads: 4(M) x 4(N) warps, 32x32 warp tiles.
// Passes: Ah*Bh always; Ah*Bl if USE_BL; Al*Bh if USE_AL.
// EPI==0: fp32*scale to outF.  EPI==1: hi/lo fp16 split of acc*scale.
// ---------------------------------------------------------------------------
template <int EPI, bool USE_AL, bool USE_BL>
__device__ __forceinline__ void gemm_core(
    const __half* __restrict__ Ah, const __half* __restrict__ Al,
    const __half* __restrict__ Bh, const __half* __restrict__ Bl,
    float scale, float* __restrict__ outF,
    __half* __restrict__ outHi, __half* __restrict__ outLo)
{
    extern __shared__ char dyn[];
    const uint32_t sbase = smem_u32(dyn);

    const int tid  = threadIdx.x;
    const int wid  = tid >> 5;
    const int lane = tid & 31;
    const int wm   = wid & 3;
    const int wn   = wid >> 2;

    const int M0 = blockIdx.y * BM;
    const int N0 = blockIdx.x * BN;

    const int comp = tid >> 7;
    const int t128 = tid & 127;
    const int ci   = t128 & 3;
    const int r0   = t128 >> 2;
    const __half* gsrc =
        (comp == 0) ? Ah : (comp == 1) ? Al : (comp == 2) ? Bh : Bl;
    const size_t gbase = (size_t)(((comp < 2) ? M0 : N0) + r0) * L;
    const uint32_t sdst0 = sbase + comp * COMP_B + r0 * PITCH + ci * 16;
    const bool doLoad = !((comp == 1 && !USE_AL) || (comp == 3 && !USE_BL));

    auto load_stage = [&](int stage, int kt) {
        if (!doLoad) return;
        const uint32_t sd = sdst0 + stage * STAGE_B;
        const size_t   gk = (size_t)kt * BK + ci * 8;
#pragma unroll
        for (int i = 0; i < 4; i++)
            cp16(sd + i * (32 * PITCH), gsrc + gbase + (size_t)(i * 32) * L + gk);
    };

    load_stage(0, 0); CP_COMMIT();
    load_stage(1, 1); CP_COMMIT();

    const uint32_t lanePart = (uint32_t)((lane & 15) * PITCH + (lane >> 4) * 16);
    const uint32_t aOffH = 0 * COMP_B + (uint32_t)(wm * 32 * PITCH) + lanePart;
    const uint32_t aOffL = 1 * COMP_B + (uint32_t)(wm * 32 * PITCH) + lanePart;
    const uint32_t bOffH = 2 * COMP_B + (uint32_t)(wn * 32 * PITCH) + lanePart;
    const uint32_t bOffL = 3 * COMP_B + (uint32_t)(wn * 32 * PITCH) + lanePart;

    float acc[2][4][4];
#pragma unroll
    for (int i = 0; i < 2; i++)
#pragma unroll
        for (int j = 0; j < 4; j++)
#pragma unroll
            for (int k = 0; k < 4; k++) acc[i][j][k] = 0.0f;

    const int NKT = L / BK;
    for (int kt = 0; kt < NKT; kt++) {
        CP_WAIT(1);
        __syncthreads();

        const uint32_t sb = sbase + (kt % STAGES) * STAGE_B;
#pragma unroll
        for (int ks = 0; ks < 2; ks++) {
            const uint32_t ko = (uint32_t)(ks * 32);
            uint32_t ah[2][4], al[2][4];
#pragma unroll
            for (int tm = 0; tm < 2; tm++) {
                ldsm4(ah[tm], sb + aOffH + (uint32_t)(tm * 16 * PITCH) + ko);
                if (USE_AL)
                    ldsm4(al[tm], sb + aOffL + (uint32_t)(tm * 16 * PITCH) + ko);
            }
            uint32_t bh[4][2], bl[4][2];
#pragma unroll
            for (int g = 0; g < 2; g++) {
                uint32_t t[4];
                ldsm4(t, sb + bOffH + (uint32_t)(g * 16 * PITCH) + ko);
                bh[2 * g][0] = t[0];     bh[2 * g][1] = t[2];
                bh[2 * g + 1][0] = t[1]; bh[2 * g + 1][1] = t[3];
                if (USE_BL) {
                    ldsm4(t, sb + bOffL + (uint32_t)(g * 16 * PITCH) + ko);
                    bl[2 * g][0] = t[0];     bl[2 * g][1] = t[2];
                    bl[2 * g + 1][0] = t[1]; bl[2 * g + 1][1] = t[3];
                }
            }
#pragma unroll
            for (int tm = 0; tm < 2; tm++)
#pragma unroll
                for (int tn = 0; tn < 4; tn++)
                    mma16816(acc[tm][tn], ah[tm], bh[tn][0], bh[tn][1]);
            if (USE_BL) {
#pragma unroll
                for (int tm = 0; tm < 2; tm++)
#pragma unroll
                    for (int tn = 0; tn < 4; tn++)
                        mma16816(acc[tm][tn], ah[tm], bl[tn][0], bl[tn][1]);
            }
            if (USE_AL) {
#pragma unroll
                for (int tm = 0; tm < 2; tm++)
#pragma unroll
                    for (int tn = 0; tn < 4; tn++)
                        mma16816(acc[tm][tn], al[tm], bh[tn][0], bh[tn][1]);
            }
        }

        __syncthreads();
        if (kt + 2 < NKT) load_stage((kt + 2) % STAGES, kt + 2);
        CP_COMMIT();
    }

    // ---- epilogue ----
    const int mBase = M0 + wm * 32 + (lane >> 2);
    const int cBase = N0 + wn * 32 + (lane & 3) * 2;
#pragma unroll
    for (int tm = 0; tm < 2; tm++)
#pragma unroll
        for (int tn = 0; tn < 4; tn++) {
            const float* a = acc[tm][tn];
            const int m = mBase + tm * 16;
            const int c = cBase + tn * 8;
            const size_t o0 = (size_t)m * L + c;
            const size_t o1 = o0 + 8 * L;
            if (EPI == 0) {
                *reinterpret_cast<float2*>(&outF[o0]) =
                    make_float2(a[0] * scale, a[1] * scale);
                *reinterpret_cast<float2*>(&outF[o1]) =
                    make_float2(a[2] * scale, a[3] * scale);
            } else {
#pragma unroll
                for (int p = 0; p < 2; p++) {
                    const float v0 = a[2 * p] * scale, v1 = a[2 * p + 1] * scale;
                    __half h0 = __float2half(v0);
                    __half h1 = __float2half(v1);
                    __half l0 = __float2half(v0 - __half2float(h0));
                    __half l1 = __float2half(v1 - __half2float(h1));
                    uint32_t hp = (uint32_t)__half_as_ushort(h0) |
                                  ((uint32_t)__half_as_ushort(h1) << 16);
                    uint32_t lp = (uint32_t)__half_as_ushort(l0) |
                                  ((uint32_t)__half_as_ushort(l1) << 16);
                    const size_t o = p ? o1 : o0;
                    *reinterpret_cast<uint32_t*>(&outHi[o]) = hp;
                    *reinterpret_cast<uint32_t*>(&outLo[o]) = lp;
                }
            }
        }
}

// ---------------------------------------------------------------------------
// G = wk . wq^T, unbatched. Inputs prescaled x256 each -> acc = 65536*G.
// Store G*16 -> scale 1/4096. 3-pass.
// ---------------------------------------------------------------------------
__global__ void __launch_bounds__(512, 1)
g_kernel(const __half* __restrict__ WKNH, const __half* __restrict__ WKNL,
         const __half* __restrict__ WQNH, const __half* __restrict__ WQNL,
         __half* __restrict__ GH, __half* __restrict__ GL)
{
    gemm_core<1, true, true>(WKNH, WKNL, WQNH, WQNL, 1.0f / 4096.0f,
                             nullptr, GH, GL);
}

// tT[e,m] = sum_m' xT[e,m'] * G16[m,m'];  stores 16*t. 3-pass, batched.
__global__ void __launch_bounds__(512, 1)
t_kernel(const __half* __restrict__ XTH, const __half* __restrict__ XTL,
         const __half* __restrict__ GH, const __half* __restrict__ GL,
         __half* __restrict__ TTH, __half* __restrict__ TTL)
{
    const size_t bo = (size_t)blockIdx.z * PER_B;
    gemm_core<1, true, true>(XTH + bo, XTL + bo, GH, GL, 1.0f,
                             nullptr, TTH + bo, TTL + bo);
}

// kq[d,e] = sum_m xT[d,m] * tT16[e,m] / 512  (= x.t/32). 3-pass, fp32 out.
__global__ void __launch_bounds__(512, 1)
kq_kernel(const __half* __restrict__ XTH, const __half* __restrict__ XTL,
          const __half* __restrict__ TTH, const __half* __restrict__ TTL,
          float* __restrict__ outF)
{
    const size_t bo = (size_t)blockIdx.z * PER_B;
    gemm_core<0, true, true>(XTH + bo, XTL + bo, TTH + bo, TTL + bo,
                             1.0f / 512.0f, outF + bo, nullptr, nullptr);
}

// u[d,m] = sum_e sm[d,e] * xN[m,e];  stores 256*u. 2-pass (sm 1-digit).
__global__ void __launch_bounds__(512, 1)
u_kernel(const __half* __restrict__ SMH,
         const __half* __restrict__ XNH, const __half* __restrict__ XNL,
         __half* __restrict__ UH, __half* __restrict__ UL)
{
    const size_t bo = (size_t)blockIdx.z * PER_B;
    gemm_core<1, false, true>(SMH + bo, nullptr, XNH + bo, XNL + bo, 256.0f,
                              nullptr, UH + bo, UL + bo);
}

// out[n,d] = sum_m wvT256[n,m] * u256[d,m] / 65536. 2-pass (wv 1-digit).
__global__ void __launch_bounds__(512, 1)
out_kernel(const __half* __restrict__ WVTH,
           const __half* __restrict__ UH, const __half* __restrict__ UL,
           float* __restrict__ outF)
{
    const size_t bo = (size_t)blockIdx.z * PER_B;
    gemm_core<0, false, true>(WVTH, nullptr, UH + bo, UL + bo,
                              1.0f / 65536.0f, outF + bo, nullptr, nullptr);
}

// ---------------------------------------------------------------------------
// Prep: z<16 -> x batch z: natural split + transposed split (prescale 1).
//       z=16 -> wk natural split x256. z=17 -> wq natural split x256.
//       z=18 -> wv transposed split x256.
// ---------------------------------------------------------------------------
__global__ void __launch_bounds__(256)
prep_split(const float* __restrict__ x,
           const float* __restrict__ wk, const float* __restrict__ wq,
           const float* __restrict__ wv,
           __half* __restrict__ XTH, __half* __restrict__ XTL,
           __half* __restrict__ XNH, __half* __restrict__ XNL,
           __half* __restrict__ WKNH, __half* __restrict__ WKNL,
           __half* __restrict__ WQNH, __half* __restrict__ WQNL,
           __half* __restrict__ WVTH, __half* __restrict__ WVTL)
{
    __shared__ float t[32][33];
    const int z = blockIdx.z;
    const int tx = threadIdx.x, ty = threadIdx.y;
    const int r0 = blockIdx.y * 32, c0 = blockIdx.x * 32;

    const float* in;
    float pres = 1.0f;
    bool doNat = false, doTr = false;
    __half *nh = nullptr, *nl = nullptr, *th = nullptr, *tl = nullptr;

    if (z < 16) {
        in = x + (size_t)z * PER_B;
        doNat = true; doTr = true;
        nh = XNH + (size_t)z * PER_B; nl = XNL + (size_t)z * PER_B;
        th = XTH + (size_t)z * PER_B; tl = XTL + (size_t)z * PER_B;
    } else if (z == 16) {
        in = wk; pres = W_PRESCALE; doNat = true;
        nh = WKNH; nl = WKNL;
    } else if (z == 17) {
        in = wq; pres = W_PRESCALE; doNat = true;
        nh = WQNH; nl = WQNL;
    } else {
        in = wv; pres = W_PRESCALE; doTr = true;
        th = WVTH; tl = WVTL;
    }

    float v[4];
#pragma unroll
    for (int i = 0; i < 4; i++)
        v[i] = in[(size_t)(r0 + ty + i * 8) * L + c0 + tx] * pres;

    if (doNat) {
#pragma unroll
        for (int i = 0; i < 4; i++) {
            __half h = __float2half(v[i]);
            __half l = __float2half(v[i] - __half2float(h));
            size_t o = (size_t)(r0 + ty + i * 8) * L + c0 + tx;
            nh[o] = h;
            nl[o] = l;
        }
    }
    if (doTr) {
#pragma unroll
        for (int i = 0; i < 4; i++) t[ty + i * 8][tx] = v[i];
        __syncthreads();
#pragma unroll
        for (int i = 0; i < 4; i++) {
            float vv = t[tx][ty + i * 8];
            __half h = __float2half(vv);
            __half l = __float2half(vv - __half2float(h));
            size_t o = (size_t)(c0 + ty + i * 8) * L + r0 + tx;
            th[o] = h;
            tl[o] = l;
        }
    }
}

// ---------------------------------------------------------------------------
// row softmax (1024 wide), output single-digit fp16
// ---------------------------------------------------------------------------
__global__ void __launch_bounds__(256)
softmax_h(const float* __restrict__ kq, __half* __restrict__ oh)
{
    const size_t rb = (size_t)blockIdx.x * L;
    const int tid = threadIdx.x;
    float4 v = *reinterpret_cast<const float4*>(&kq[rb + tid * 4]);

    __shared__ float red[8];
    const int lane = tid & 31, wid = tid >> 5;

    float m = fmaxf(fmaxf(v.x, v.y), fmaxf(v.z, v.w));
#pragma unroll
    for (int o = 16; o; o >>= 1) m = fmaxf(m, __shfl_xor_sync(0xffffffffu, m, o));
    if (lane == 0) red[wid] = m;
    __syncthreads();
    m = red[0];
#pragma unroll
    for (int w = 1; w < 8; w++) m = fmaxf(m, red[w]);
    __syncthreads();

    v.x = expf(v.x - m); v.y = expf(v.y - m);
    v.z = expf(v.z - m); v.w = expf(v.w - m);
    float s = v.x + v.y + v.z + v.w;
#pragma unroll
    for (int o = 16; o; o >>= 1) s += __shfl_xor_sync(0xffffffffu, s, o);
    if (lane == 0) red[wid] = s;
    __syncthreads();
    s = red[0];
#pragma unroll
    for (int w = 1; w < 8; w++) s += red[w];

    const float inv = 1.0f / s;
    uint32_t p0 = (uint32_t)__half_as_ushort(__float2half(v.x * inv)) |
                  ((uint32_t)__half_as_ushort(__float2half(v.y * inv)) << 16);
    uint32_t p1 = (uint32_t)__half_as_ushort(__float2half(v.z * inv)) |
                  ((uint32_t)__half_as_ushort(__float2half(v.w * inv)) << 16);
    *reinterpret_cast<uint2*>(&oh[rb + tid * 4]) = make_uint2(p0, p1);
}

// ---------------------------------------------------------------------------
// host
// ---------------------------------------------------------------------------
extern "C" void kernel_launch(void* const* d_in, const int* in_sizes, int n_in,
                              void* d_out, int out_size)
{
    (void)in_sizes; (void)n_in; (void)out_size;
    const float* x  = (const float*)d_in[0];
    const float* wk = (const float*)d_in[1];
    const float* wq = (const float*)d_in[2];
    const float* wv = (const float*)d_in[3];
    float* out = (float*)d_out;

    void *xth, *xtl, *xnh, *xnl, *tth, *ttl, *smh, *uh, *ul;
    void *gh, *gl, *wknh, *wknl, *wqnh, *wqnl, *wvth, *wvtl, *kq;
    cudaGetSymbolAddress(&xth, g_xT_hi);  cudaGetSymbolAddress(&xtl, g_xT_lo);
    cudaGetSymbolAddress(&xnh, g_xN_hi);  cudaGetSymbolAddress(&xnl, g_xN_lo);
    cudaGetSymbolAddress(&tth, g_tT_hi);  cudaGetSymbolAddress(&ttl, g_tT_lo);
    cudaGetSymbolAddress(&smh, g_sm_hi);
    cudaGetSymbolAddress(&uh, g_u_hi);    cudaGetSymbolAddress(&ul, g_u_lo);
    cudaGetSymbolAddress(&gh, g_G_hi);    cudaGetSymbolAddress(&gl, g_G_lo);
    cudaGetSymbolAddress(&wknh, g_wkN_hi); cudaGetSymbolAddress(&wknl, g_wkN_lo);
    cudaGetSymbolAddress(&wqnh, g_wqN_hi); cudaGetSymbolAddress(&wqnl, g_wqN_lo);
    cudaGetSymbolAddress(&wvth, g_wvT_hi); cudaGetSymbolAddress(&wvtl, g_wvT_lo);
    cudaGetSymbolAddress(&kq, g_kq);

    cudaFuncSetAttribute((const void*)g_kernel,
                         cudaFuncAttributeMaxDynamicSharedMemorySize, SMEM_DYN);
    cudaFuncSetAttribute((const void*)t_kernel,
                         cudaFuncAttributeMaxDynamicSharedMemorySize, SMEM_DYN);
    cudaFuncSetAttribute((const void*)kq_kernel,
                         cudaFuncAttributeMaxDynamicSharedMemorySize, SMEM_DYN);
    cudaFuncSetAttribute((const void*)u_kernel,
                         cudaFuncAttributeMaxDynamicSharedMemorySize, SMEM_DYN);
    cudaFuncSetAttribute((const void*)out_kernel,
                         cudaFuncAttributeMaxDynamicSharedMemorySize, SMEM_DYN);

    // prep: x -> XT + XN (16 z's); wk,wq natural; wv transposed
    prep_split<<<dim3(32, 32, 19), dim3(32, 8)>>>(
        x, wk, wq, wv,
        (__half*)xth, (__half*)xtl, (__half*)xnh, (__half*)xnl,
        (__half*)wknh, (__half*)wknl, (__half*)wqnh, (__half*)wqnl,
        (__half*)wvth, (__half*)wvtl);

    // G = wk.wq^T (unbatched)
    g_kernel<<<dim3(8, 8, 1), 512, SMEM_DYN>>>(
        (__half*)wknh, (__half*)wknl, (__half*)wqnh, (__half*)wqnl,
        (__half*)gh, (__half*)gl);

    // tT = xT . G  (batched)
    t_kernel<<<dim3(8, 8, BATCH), 512, SMEM_DYN>>>(
        (__half*)xth, (__half*)xtl, (__half*)gh, (__half*)gl,
        (__half*)tth, (__half*)ttl);

    // kq = xT . tT / 32
    kq_kernel<<<dim3(8, 8, BATCH), 512, SMEM_DYN>>>(
        (__half*)xth, (__half*)xtl, (__half*)tth, (__half*)ttl, (float*)kq);

    // softmax -> sm (1 digit)
    softmax_h<<<BATCH * L, 256>>>((const float*)kq, (__half*)smh);

    // u = sm . xN
    u_kernel<<<dim3(8, 8, BATCH), 512, SMEM_DYN>>>(
        (__half*)smh, (__half*)xnh, (__half*)xnl, (__half*)uh, (__half*)ul);

    // out = wvT . u
    out_kernel<<<dim3(8, 8, BATCH), 512, SMEM_DYN>>>(
        (__half*)wvth, (__half*)uh, (__half*)ul, out);
}

// round 7
// speedup vs baseline: 2.6931x; 1.1235x over previous
#include <cuda_runtime.h>
#include <cuda_fp16.h>
#include <cstdint>
#include <cstddef>

// ===========================================================================
// SelfAttention via mma.sync.m16n8k16 (fp16 digits, fp32 acc), split-fp16
// multi-pass fp32 emulation, restructured algebra:
//   G  = wk . wq^T   (unbatched, 3-pass)
//   tT = xT . G      (batched, 3-pass)
//   kq = xT . tT /32 (batched, 3-pass)
//   sm = softmax(kq)
//   u  = sm . xN     (batched, 2-pass)
//   out= wvT . u     (batched, 2-pass)
// GEMM core: 128x64 CTA tile, 256 threads, 3-stage cp.async, ONE barrier
// per k-tile, 92KB smem -> 2 CTAs/SM for barrier/epilogue overlap.
// ===========================================================================

#define L 1024
#define BATCH 16
#define PER_B ((size_t)L * L)
#define ELTS ((size_t)BATCH * L * L)

#define BM 128
#define BN 64
#define BK 32
#define STAGES 3
#define PITCH 80                         // 64B data + 16B pad per 32-fp16 row
#define A_COMP (128 * PITCH)             // 10240 B
#define B_COMP (64 * PITCH)              // 5120 B
#define OFF_AH 0
#define OFF_AL (A_COMP)                  // 10240
#define OFF_BH (2 * A_COMP)              // 20480
#define OFF_BL (2 * A_COMP + B_COMP)     // 25600
#define STAGE_B (2 * A_COMP + 2 * B_COMP)  // 30720
#define SMEM_DYN (STAGES * STAGE_B)      // 92160

#define W_PRESCALE 256.0f

// ---- scratch (device globals; cudaMalloc forbidden) ----
__device__ __align__(1024) __half g_xT_hi[ELTS], g_xT_lo[ELTS];   // x transposed
__device__ __align__(1024) __half g_xN_hi[ELTS], g_xN_lo[ELTS];   // x natural
__device__ __align__(1024) __half g_tT_hi[ELTS], g_tT_lo[ELTS];   // (xT.G) * 16
__device__ __align__(1024) __half g_sm_hi[ELTS];                  // softmax, 1 digit
__device__ __align__(1024) __half g_u_hi[ELTS],  g_u_lo[ELTS];    // (sm.xN) * 256
__device__ __align__(1024) __half g_G_hi[L * L], g_G_lo[L * L];   // wk.wq^T * 16
__device__ __align__(1024) __half g_wkN_hi[L * L], g_wkN_lo[L * L];  // *256
__device__ __align__(1024) __half g_wqN_hi[L * L], g_wqN_lo[L * L];  // *256
__device__ __align__(1024) __half g_wvT_hi[L * L], g_wvT_lo[L * L];  // *256
__device__ __align__(1024) float g_kq[ELTS];

// ---------------------------------------------------------------------------
__device__ __forceinline__ uint32_t smem_u32(const void* p) {
    uint32_t a;
    asm("{ .reg .u64 t; cvta.to.shared.u64 t, %1; cvt.u32.u64 %0, t; }"
        : "=r"(a) : "l"(p));
    return a;
}

__device__ __forceinline__ void cp16(uint32_t dst, const void* src) {
    asm volatile("cp.async.cg.shared.global [%0], [%1], 16;"
                 :: "r"(dst), "l"(src) : "memory");
}
#define CP_COMMIT() asm volatile("cp.async.commit_group;" ::: "memory")
#define CP_WAIT(n)  asm volatile("cp.async.wait_group %0;" :: "n"(n) : "memory")

__device__ __forceinline__ void ldsm4(uint32_t* r, uint32_t addr) {
    asm volatile("ldmatrix.sync.aligned.m8n8.x4.shared.b16 {%0,%1,%2,%3}, [%4];"
                 : "=r"(r[0]), "=r"(r[1]), "=r"(r[2]), "=r"(r[3]) : "r"(addr));
}

__device__ __forceinline__ void mma16816(float* d, const uint32_t* a,
                                         uint32_t b0, uint32_t b1) {
    asm volatile(
        "mma.sync.aligned.m16n8k16.row.col.f32.f16.f16.f32 "
        "{%0,%1,%2,%3}, {%4,%5,%6,%7}, {%8,%9}, {%0,%1,%2,%3};"
        : "+f"(d[0]), "+f"(d[1]), "+f"(d[2]), "+f"(d[3])
        : "r"(a[0]), "r"(a[1]), "r"(a[2]), "r"(a[3]), "r"(b0), "r"(b1));
}

// ---------------------------------------------------------------------------
// Core GEMM: D[i][j] = sum_k A[i][k]*B[j][k] for one 1024x1024 problem.
// 256 threads: 4(M) x 2(N) warps, 32x32 warp tiles, CTA tile 128x64.
// Passes: Ah*Bh always; Ah*Bl if USE_BL; Al*Bh if USE_AL.
// EPI==0: fp32*scale to outF.  EPI==1: hi/lo fp16 split of acc*scale.
// ---------------------------------------------------------------------------
template <int EPI, bool USE_AL, bool USE_BL>
__device__ __forceinline__ void gemm_core(
    const __half* __restrict__ Ah, const __half* __restrict__ Al,
    const __half* __restrict__ Bh, const __half* __restrict__ Bl,
    float scale, float* __restrict__ outF,
    __half* __restrict__ outHi, __half* __restrict__ outLo)
{
    extern __shared__ char dyn[];
    const uint32_t sbase = smem_u32(dyn);

    const int tid  = threadIdx.x;
    const int wid  = tid >> 5;
    const int lane = tid & 31;
    const int wm   = wid & 3;            // 4 warps along M
    const int wn   = wid >> 2;           // 2 warps along N

    const int M0 = blockIdx.y * BM;
    const int N0 = blockIdx.x * BN;

    // ---- cp.async mapping: every thread loads up to 6 16B chunks/stage ----
    const int ci = tid & 3;              // 16B chunk in row (k-offset ci*8)
    const int r0 = tid >> 2;             // row 0..63
    const __half* gAh = Ah + (size_t)(M0 + r0) * L;
    const __half* gAl = USE_AL ? (Al + (size_t)(M0 + r0) * L) : nullptr;
    const __half* gBh = Bh + (size_t)(N0 + r0) * L;
    const __half* gBl = USE_BL ? (Bl + (size_t)(N0 + r0) * L) : nullptr;
    const uint32_t sA = r0 * PITCH + ci * 16;
    const uint32_t sA2 = (r0 + 64) * PITCH + ci * 16;
    const size_t gA2 = (size_t)64 * L;

    auto load_stage = [&](int stage, int kt) {
        const uint32_t sb = sbase + stage * STAGE_B;
        const size_t   gk = (size_t)kt * BK + ci * 8;
        cp16(sb + OFF_AH + sA,  gAh + gk);
        cp16(sb + OFF_AH + sA2, gAh + gA2 + gk);
        if (USE_AL) {
            cp16(sb + OFF_AL + sA,  gAl + gk);
            cp16(sb + OFF_AL + sA2, gAl + gA2 + gk);
        }
        cp16(sb + OFF_BH + sA, gBh + gk);
        if (USE_BL)
            cp16(sb + OFF_BL + sA, gBl + gk);
    };

    load_stage(0, 0); CP_COMMIT();
    load_stage(1, 1); CP_COMMIT();

    const uint32_t lanePart = (uint32_t)((lane & 15) * PITCH + (lane >> 4) * 16);
    const uint32_t aOffH = OFF_AH + (uint32_t)(wm * 32 * PITCH) + lanePart;
    const uint32_t aOffL = OFF_AL + (uint32_t)(wm * 32 * PITCH) + lanePart;
    const uint32_t bOffH = OFF_BH + (uint32_t)(wn * 32 * PITCH) + lanePart;
    const uint32_t bOffL = OFF_BL + (uint32_t)(wn * 32 * PITCH) + lanePart;

    float acc[2][4][4];
#pragma unroll
    for (int i = 0; i < 2; i++)
#pragma unroll
        for (int j = 0; j < 4; j++)
#pragma unroll
            for (int k = 0; k < 4; k++) acc[i][j][k] = 0.0f;

    const int NKT = L / BK;              // 32
    for (int kt = 0; kt < NKT; kt++) {
        CP_WAIT(1);
        __syncthreads();                 // single barrier per k-tile

        // issue next loads immediately (stage (kt+2)%3 was read in iter kt-1)
        if (kt + 2 < NKT) load_stage((kt + 2) % STAGES, kt + 2);
        CP_COMMIT();

        const uint32_t sb = sbase + (kt % STAGES) * STAGE_B;
#pragma unroll
        for (int ks = 0; ks < 2; ks++) {
            const uint32_t ko = (uint32_t)(ks * 32);
            uint32_t ah[2][4], al[2][4];
#pragma unroll
            for (int tm = 0; tm < 2; tm++) {
                ldsm4(ah[tm], sb + aOffH + (uint32_t)(tm * 16 * PITCH) + ko);
                if (USE_AL)
                    ldsm4(al[tm], sb + aOffL + (uint32_t)(tm * 16 * PITCH) + ko);
            }
            uint32_t bh[4][2], bl[4][2];
#pragma unroll
            for (int g = 0; g < 2; g++) {
                uint32_t t[4];
                ldsm4(t, sb + bOffH + (uint32_t)(g * 16 * PITCH) + ko);
                bh[2 * g][0] = t[0];     bh[2 * g][1] = t[2];
                bh[2 * g + 1][0] = t[1]; bh[2 * g + 1][1] = t[3];
                if (USE_BL) {
                    ldsm4(t, sb + bOffL + (uint32_t)(g * 16 * PITCH) + ko);
                    bl[2 * g][0] = t[0];     bl[2 * g][1] = t[2];
                    bl[2 * g + 1][0] = t[1]; bl[2 * g + 1][1] = t[3];
                }
            }
#pragma unroll
            for (int tm = 0; tm < 2; tm++)
#pragma unroll
                for (int tn = 0; tn < 4; tn++)
                    mma16816(acc[tm][tn], ah[tm], bh[tn][0], bh[tn][1]);
            if (USE_BL) {
#pragma unroll
                for (int tm = 0; tm < 2; tm++)
#pragma unroll
                    for (int tn = 0; tn < 4; tn++)
                        mma16816(acc[tm][tn], ah[tm], bl[tn][0], bl[tn][1]);
            }
            if (USE_AL) {
#pragma unroll
                for (int tm = 0; tm < 2; tm++)
#pragma unroll
                    for (int tn = 0; tn < 4; tn++)
                        mma16816(acc[tm][tn], al[tm], bh[tn][0], bh[tn][1]);
            }
        }
    }

    // ---- epilogue ----
    const int mBase = M0 + wm * 32 + (lane >> 2);
    const int cBase = N0 + wn * 32 + (lane & 3) * 2;
#pragma unroll
    for (int tm = 0; tm < 2; tm++)
#pragma unroll
        for (int tn = 0; tn < 4; tn++) {
            const float* a = acc[tm][tn];
            const int m = mBase + tm * 16;
            const int c = cBase + tn * 8;
            const size_t o0 = (size_t)m * L + c;
            const size_t o1 = o0 + 8 * L;
            if (EPI == 0) {
                *reinterpret_cast<float2*>(&outF[o0]) =
                    make_float2(a[0] * scale, a[1] * scale);
                *reinterpret_cast<float2*>(&outF[o1]) =
                    make_float2(a[2] * scale, a[3] * scale);
            } else {
#pragma unroll
                for (int p = 0; p < 2; p++) {
                    const float v0 = a[2 * p] * scale, v1 = a[2 * p + 1] * scale;
                    __half h0 = __float2half(v0);
                    __half h1 = __float2half(v1);
                    __half l0 = __float2half(v0 - __half2float(h0));
                    __half l1 = __float2half(v1 - __half2float(h1));
                    uint32_t hp = (uint32_t)__half_as_ushort(h0) |
                                  ((uint32_t)__half_as_ushort(h1) << 16);
                    uint32_t lp = (uint32_t)__half_as_ushort(l0) |
                                  ((uint32_t)__half_as_ushort(l1) << 16);
                    const size_t o = p ? o1 : o0;
                    *reinterpret_cast<uint32_t*>(&outHi[o]) = hp;
                    *reinterpret_cast<uint32_t*>(&outLo[o]) = lp;
                }
            }
        }
}

// ---------------------------------------------------------------------------
// kernels (grid: x = L/BN = 16, y = L/BM = 8, z = batch)
// ---------------------------------------------------------------------------
__global__ void __launch_bounds__(256, 2)
g_kernel(const __half* __restrict__ WKNH, const __half* __restrict__ WKNL,
         const __half* __restrict__ WQNH, const __half* __restrict__ WQNL,
         __half* __restrict__ GH, __half* __restrict__ GL)
{
    // G = wk.wq^T; inputs x256 each -> store G*16 -> scale 1/4096. 3-pass.
    gemm_core<1, true, true>(WKNH, WKNL, WQNH, WQNL, 1.0f / 4096.0f,
                             nullptr, GH, GL);
}

__global__ void __launch_bounds__(256, 2)
t_kernel(const __half* __restrict__ XTH, const __half* __restrict__ XTL,
         const __half* __restrict__ GH, const __half* __restrict__ GL,
         __half* __restrict__ TTH, __half* __restrict__ TTL)
{
    // tT = xT.G16 (stores 16*t). 3-pass.
    const size_t bo = (size_t)blockIdx.z * PER_B;
    gemm_core<1, true, true>(XTH + bo, XTL + bo, GH, GL, 1.0f,
                             nullptr, TTH + bo, TTL + bo);
}

__global__ void __launch_bounds__(256, 2)
kq_kernel(const __half* __restrict__ XTH, const __half* __restrict__ XTL,
          const __half* __restrict__ TTH, const __half* __restrict__ TTL,
          float* __restrict__ outF)
{
    // kq = xT.tT16 / 512 (= x.t/32). 3-pass, fp32 out.
    const size_t bo = (size_t)blockIdx.z * PER_B;
    gemm_core<0, true, true>(XTH + bo, XTL + bo, TTH + bo, TTL + bo,
                             1.0f / 512.0f, outF + bo, nullptr, nullptr);
}

__global__ void __launch_bounds__(256, 2)
u_kernel(const __half* __restrict__ SMH,
         const __half* __restrict__ XNH, const __half* __restrict__ XNL,
         __half* __restrict__ UH, __half* __restrict__ UL)
{
    // u = sm.xN (stores 256*u). 2-pass (sm 1-digit).
    const size_t bo = (size_t)blockIdx.z * PER_B;
    gemm_core<1, false, true>(SMH + bo, nullptr, XNH + bo, XNL + bo, 256.0f,
                              nullptr, UH + bo, UL + bo);
}

__global__ void __launch_bounds__(256, 2)
out_kernel(const __half* __restrict__ WVTH,
           const __half* __restrict__ UH, const __half* __restrict__ UL,
           float* __restrict__ outF)
{
    // out = wvT256.u256 / 65536. 2-pass (wv 1-digit).
    const size_t bo = (size_t)blockIdx.z * PER_B;
    gemm_core<0, false, true>(WVTH, nullptr, UH + bo, UL + bo,
                              1.0f / 65536.0f, outF + bo, nullptr, nullptr);
}

// ---------------------------------------------------------------------------
// Prep: z<16 -> x batch z: natural + transposed splits (prescale 1).
//       z=16 -> wk natural x256. z=17 -> wq natural x256. z=18 -> wv transp x256.
// ---------------------------------------------------------------------------
__global__ void __launch_bounds__(256)
prep_split(const float* __restrict__ x,
           const float* __restrict__ wk, const float* __restrict__ wq,
           const float* __restrict__ wv,
           __half* __restrict__ XTH, __half* __restrict__ XTL,
           __half* __restrict__ XNH, __half* __restrict__ XNL,
           __half* __restrict__ WKNH, __half* __restrict__ WKNL,
           __half* __restrict__ WQNH, __half* __restrict__ WQNL,
           __half* __restrict__ WVTH, __half* __restrict__ WVTL)
{
    __shared__ float t[32][33];
    const int z = blockIdx.z;
    const int tx = threadIdx.x, ty = threadIdx.y;
    const int r0 = blockIdx.y * 32, c0 = blockIdx.x * 32;

    const float* in;
    float pres = 1.0f;
    bool doNat = false, doTr = false;
    __half *nh = nullptr, *nl = nullptr, *th = nullptr, *tl = nullptr;

    if (z < 16) {
        in = x + (size_t)z * PER_B;
        doNat = true; doTr = true;
        nh = XNH + (size_t)z * PER_B; nl = XNL + (size_t)z * PER_B;
        th = XTH + (size_t)z * PER_B; tl = XTL + (size_t)z * PER_B;
    } else if (z == 16) {
        in = wk; pres = W_PRESCALE; doNat = true;
        nh = WKNH; nl = WKNL;
    } else if (z == 17) {
        in = wq; pres = W_PRESCALE; doNat = true;
        nh = WQNH; nl = WQNL;
    } else {
        in = wv; pres = W_PRESCALE; doTr = true;
        th = WVTH; tl = WVTL;
    }

    float v[4];
#pragma unroll
    for (int i = 0; i < 4; i++)
        v[i] = in[(size_t)(r0 + ty + i * 8) * L + c0 + tx] * pres;

    if (doNat) {
#pragma unroll
        for (int i = 0; i < 4; i++) {
            __half h = __float2half(v[i]);
            __half l = __float2half(v[i] - __half2float(h));
            size_t o = (size_t)(r0 + ty + i * 8) * L + c0 + tx;
            nh[o] = h;
            nl[o] = l;
        }
    }
    if (doTr) {
#pragma unroll
        for (int i = 0; i < 4; i++) t[ty + i * 8][tx] = v[i];
        __syncthreads();
#pragma unroll
        for (int i = 0; i < 4; i++) {
            float vv = t[tx][ty + i * 8];
            __half h = __float2half(vv);
            __half l = __float2half(vv - __half2float(h));
            size_t o = (size_t)(c0 + ty + i * 8) * L + r0 + tx;
            th[o] = h;
            tl[o] = l;
        }
    }
}

// ---------------------------------------------------------------------------
// row softmax (1024 wide), output single-digit fp16
// ---------------------------------------------------------------------------
__global__ void __launch_bounds__(256)
softmax_h(const float* __restrict__ kq, __half* __restrict__ oh)
{
    const size_t rb = (size_t)blockIdx.x * L;
    const int tid = threadIdx.x;
    float4 v = *reinterpret_cast<const float4*>(&kq[rb + tid * 4]);

    __shared__ float red[8];
    const int lane = tid & 31, wid = tid >> 5;

    float m = fmaxf(fmaxf(v.x, v.y), fmaxf(v.z, v.w));
#pragma unroll
    for (int o = 16; o; o >>= 1) m = fmaxf(m, __shfl_xor_sync(0xffffffffu, m, o));
    if (lane == 0) red[wid] = m;
    __syncthreads();
    m = red[0];
#pragma unroll
    for (int w = 1; w < 8; w++) m = fmaxf(m, red[w]);
    __syncthreads();

    v.x = expf(v.x - m); v.y = expf(v.y - m);
    v.z = expf(v.z - m); v.w = expf(v.w - m);
    float s = v.x + v.y + v.z + v.w;
#pragma unroll
    for (int o = 16; o; o >>= 1) s += __shfl_xor_sync(0xffffffffu, s, o);
    if (lane == 0) red[wid] = s;
    __syncthreads();
    s = red[0];
#pragma unroll
    for (int w = 1; w < 8; w++) s += red[w];

    const float inv = 1.0f / s;
    uint32_t p0 = (uint32_t)__half_as_ushort(__float2half(v.x * inv)) |
                  ((uint32_t)__half_as_ushort(__float2half(v.y * inv)) << 16);
    uint32_t p1 = (uint32_t)__half_as_ushort(__float2half(v.z * inv)) |
                  ((uint32_t)__half_as_ushort(__float2half(v.w * inv)) << 16);
    *reinterpret_cast<uint2*>(&oh[rb + tid * 4]) = make_uint2(p0, p1);
}

// ---------------------------------------------------------------------------
// host
// ---------------------------------------------------------------------------
extern "C" void kernel_launch(void* const* d_in, const int* in_sizes, int n_in,
                              void* d_out, int out_size)
{
    (void)in_sizes; (void)n_in; (void)out_size;
    const float* x  = (const float*)d_in[0];
    const float* wk = (const float*)d_in[1];
    const float* wq = (const float*)d_in[2];
    const float* wv = (const float*)d_in[3];
    float* out = (float*)d_out;

    void *xth, *xtl, *xnh, *xnl, *tth, *ttl, *smh, *uh, *ul;
    void *gh, *gl, *wknh, *wknl, *wqnh, *wqnl, *wvth, *wvtl, *kq;
    cudaGetSymbolAddress(&xth, g_xT_hi);  cudaGetSymbolAddress(&xtl, g_xT_lo);
    cudaGetSymbolAddress(&xnh, g_xN_hi);  cudaGetSymbolAddress(&xnl, g_xN_lo);
    cudaGetSymbolAddress(&tth, g_tT_hi);  cudaGetSymbolAddress(&ttl, g_tT_lo);
    cudaGetSymbolAddress(&smh, g_sm_hi);
    cudaGetSymbolAddress(&uh, g_u_hi);    cudaGetSymbolAddress(&ul, g_u_lo);
    cudaGetSymbolAddress(&gh, g_G_hi);    cudaGetSymbolAddress(&gl, g_G_lo);
    cudaGetSymbolAddress(&wknh, g_wkN_hi); cudaGetSymbolAddress(&wknl, g_wkN_lo);
    cudaGetSymbolAddress(&wqnh, g_wqN_hi); cudaGetSymbolAddress(&wqnl, g_wqN_lo);
    cudaGetSymbolAddress(&wvth, g_wvT_hi); cudaGetSymbolAddress(&wvtl, g_wvT_lo);
    cudaGetSymbolAddress(&kq, g_kq);

    cudaFuncSetAttribute((const void*)g_kernel,
                         cudaFuncAttributeMaxDynamicSharedMemorySize, SMEM_DYN);
    cudaFuncSetAttribute((const void*)t_kernel,
                         cudaFuncAttributeMaxDynamicSharedMemorySize, SMEM_DYN);
    cudaFuncSetAttribute((const void*)kq_kernel,
                         cudaFuncAttributeMaxDynamicSharedMemorySize, SMEM_DYN);
    cudaFuncSetAttribute((const void*)u_kernel,
                         cudaFuncAttributeMaxDynamicSharedMemorySize, SMEM_DYN);
    cudaFuncSetAttribute((const void*)out_kernel,
                         cudaFuncAttributeMaxDynamicSharedMemorySize, SMEM_DYN);

    // prep: x -> XT + XN (16 z's); wk,wq natural; wv transposed
    prep_split<<<dim3(32, 32, 19), dim3(32, 8)>>>(
        x, wk, wq, wv,
        (__half*)xth, (__half*)xtl, (__half*)xnh, (__half*)xnl,
        (__half*)wknh, (__half*)wknl, (__half*)wqnh, (__half*)wqnl,
        (__half*)wvth, (__half*)wvtl);

    const dim3 gg(L / BN, L / BM, BATCH);     // 16 x 8 x 16

    // G = wk.wq^T (unbatched)
    g_kernel<<<dim3(L / BN, L / BM, 1), 256, SMEM_DYN>>>(
        (__half*)wknh, (__half*)wknl, (__half*)wqnh, (__half*)wqnl,
        (__half*)gh, (__half*)gl);

    // tT = xT . G
    t_kernel<<<gg, 256, SMEM_DYN>>>(
        (__half*)xth, (__half*)xtl, (__half*)gh, (__half*)gl,
        (__half*)tth, (__half*)ttl);

    // kq = xT . tT / 32
    kq_kernel<<<gg, 256, SMEM_DYN>>>(
        (__half*)xth, (__half*)xtl, (__half*)tth, (__half*)ttl, (float*)kq);

    // softmax -> sm (1 digit)
    softmax_h<<<BATCH * L, 256>>>((const float*)kq, (__half*)smh);

    // u = sm . xN
    u_kernel<<<gg, 256, SMEM_DYN>>>(
        (__half*)smh, (__half*)xnh, (__half*)xnl, (__half*)uh, (__half*)ul);

    // out = wvT . u
    out_kernel<<<gg, 256, SMEM_DYN>>>(
        (__half*)wvth, (__half*)uh, (__half*)ul, out);
}

// round 8
// speedup vs baseline: 2.7678x; 1.0277x over previous
#include <cuda_runtime.h>
#include <cuda_fp16.h>
#include <cstdint>
#include <cstddef>

// ===========================================================================
// SelfAttention via mma.sync.m16n8k16 (fp16 digits, fp32 acc), split-fp16
// multi-pass fp32 emulation, restructured algebra:
//   G  = wk . wq^T   (unbatched, 3-pass)
//   tT = xT . G      (batched, 3-pass)
//   kq = xT . tT /32 (batched, 3-pass)
//   sm = softmax(kq)
//   u  = sm . xN     (batched, 2-pass)
//   out= wvT . u     (batched, 2-pass)
// GEMM core: 128x64 CTA tile, 256 threads, BK=16, 4-stage cp.async,
// one barrier per k-tile, 72KB smem + <=85 regs -> 3 CTAs/SM (24 warps).
// ===========================================================================

#define L 1024
#define BATCH 16
#define PER_B ((size_t)L * L)
#define ELTS ((size_t)BATCH * L * L)

#define BM 128
#define BN 64
#define BK 16
#define STAGES 4
#define PITCH 48                         // 32B data + 16B pad per 16-fp16 row
#define A_COMP (128 * PITCH)             // 6144 B
#define B_COMP (64 * PITCH)              // 3072 B
#define OFF_AH 0
#define OFF_AL (A_COMP)                  // 6144
#define OFF_BH (2 * A_COMP)              // 12288
#define OFF_BL (2 * A_COMP + B_COMP)     // 15360
#define STAGE_B (2 * A_COMP + 2 * B_COMP)  // 18432
#define SMEM_DYN (STAGES * STAGE_B)      // 73728

#define W_PRESCALE 256.0f

// ---- scratch (device globals; cudaMalloc forbidden) ----
__device__ __align__(1024) __half g_xT_hi[ELTS], g_xT_lo[ELTS];   // x transposed
__device__ __align__(1024) __half g_xN_hi[ELTS], g_xN_lo[ELTS];   // x natural
__device__ __align__(1024) __half g_tT_hi[ELTS], g_tT_lo[ELTS];   // (xT.G) * 16
__device__ __align__(1024) __half g_sm_hi[ELTS];                  // softmax, 1 digit
__device__ __align__(1024) __half g_u_hi[ELTS],  g_u_lo[ELTS];    // (sm.xN) * 256
__device__ __align__(1024) __half g_G_hi[L * L], g_G_lo[L * L];   // wk.wq^T * 16
__device__ __align__(1024) __half g_wkN_hi[L * L], g_wkN_lo[L * L];  // *256
__device__ __align__(1024) __half g_wqN_hi[L * L], g_wqN_lo[L * L];  // *256
__device__ __align__(1024) __half g_wvT_hi[L * L], g_wvT_lo[L * L];  // *256
__device__ __align__(1024) float g_kq[ELTS];

// ---------------------------------------------------------------------------
__device__ __forceinline__ uint32_t smem_u32(const void* p) {
    uint32_t a;
    asm("{ .reg .u64 t; cvta.to.shared.u64 t, %1; cvt.u32.u64 %0, t; }"
        : "=r"(a) : "l"(p));
    return a;
}

__device__ __forceinline__ void cp16(uint32_t dst, const void* src) {
    asm volatile("cp.async.cg.shared.global [%0], [%1], 16;"
                 :: "r"(dst), "l"(src) : "memory");
}
#define CP_COMMIT() asm volatile("cp.async.commit_group;" ::: "memory")
#define CP_WAIT(n)  asm volatile("cp.async.wait_group %0;" :: "n"(n) : "memory")

__device__ __forceinline__ void ldsm4(uint32_t* r, uint32_t addr) {
    asm volatile("ldmatrix.sync.aligned.m8n8.x4.shared.b16 {%0,%1,%2,%3}, [%4];"
                 : "=r"(r[0]), "=r"(r[1]), "=r"(r[2]), "=r"(r[3]) : "r"(addr));
}

__device__ __forceinline__ void mma16816(float* d, const uint32_t* a,
                                         uint32_t b0, uint32_t b1) {
    asm volatile(
        "mma.sync.aligned.m16n8k16.row.col.f32.f16.f16.f32 "
        "{%0,%1,%2,%3}, {%4,%5,%6,%7}, {%8,%9}, {%0,%1,%2,%3};"
        : "+f"(d[0]), "+f"(d[1]), "+f"(d[2]), "+f"(d[3])
        : "r"(a[0]), "r"(a[1]), "r"(a[2]), "r"(a[3]), "r"(b0), "r"(b1));
}

// ---------------------------------------------------------------------------
// Core GEMM: D[i][j] = sum_k A[i][k]*B[j][k] for one 1024x1024 problem.
// 256 threads: 4(M) x 2(N) warps, 32x32 warp tiles, CTA tile 128x64, BK=16.
// Passes: Ah*Bh always; Ah*Bl if USE_BL; Al*Bh if USE_AL.
// EPI==0: fp32*scale to outF.  EPI==1: hi/lo fp16 split of acc*scale.
// ---------------------------------------------------------------------------
template <int EPI, bool USE_AL, bool USE_BL>
__device__ __forceinline__ void gemm_core(
    const __half* __restrict__ Ah, const __half* __restrict__ Al,
    const __half* __restrict__ Bh, const __half* __restrict__ Bl,
    float scale, float* __restrict__ outF,
    __half* __restrict__ outHi, __half* __restrict__ outLo)
{
    extern __shared__ char dyn[];
    const uint32_t sbase = smem_u32(dyn);

    const int tid  = threadIdx.x;
    const int wid  = tid >> 5;
    const int lane = tid & 31;
    const int wm   = wid & 3;            // 4 warps along M
    const int wn   = wid >> 2;           // 2 warps along N

    const int M0 = blockIdx.y * BM;
    const int N0 = blockIdx.x * BN;

    // ---- cp.async mapping: 16B chunks. ci = tid&1, rr = tid>>1 (0..127).
    //   all threads: Ah[rr] (+Al[rr] if USE_AL)
    //   rr<64:  Bh[rr];  rr>=64: Bl[rr-64] (if USE_BL)
    const int ci = tid & 1;
    const int rr = tid >> 1;
    const __half* gAh = Ah + (size_t)(M0 + rr) * L;
    const __half* gAl = USE_AL ? (Al + (size_t)(M0 + rr) * L) : nullptr;
    const bool  isBh = (rr < 64);
    const int   br   = isBh ? rr : (rr - 64);
    const __half* gB = (isBh ? Bh : (USE_BL ? Bl : nullptr)) + (size_t)(N0 + br) * L;
    const bool  doB  = isBh || USE_BL;
    const uint32_t sAoff = rr * PITCH + ci * 16;
    const uint32_t sBoff = (isBh ? OFF_BH : OFF_BL) + br * PITCH + ci * 16;

    auto load_stage = [&](int stage, int kt) {
        const uint32_t sb = sbase + stage * STAGE_B;
        const size_t   gk = (size_t)kt * BK + ci * 8;
        cp16(sb + OFF_AH + sAoff, gAh + gk);
        if (USE_AL) cp16(sb + OFF_AL + sAoff, gAl + gk);
        if (doB)    cp16(sb + sBoff, gB + gk);
    };

    load_stage(0, 0); CP_COMMIT();
    load_stage(1, 1); CP_COMMIT();
    load_stage(2, 2); CP_COMMIT();

    const uint32_t lanePart = (uint32_t)((lane & 15) * PITCH + (lane >> 4) * 16);
    const uint32_t aOffH = OFF_AH + (uint32_t)(wm * 32 * PITCH) + lanePart;
    const uint32_t aOffL = OFF_AL + (uint32_t)(wm * 32 * PITCH) + lanePart;
    const uint32_t bOffH = OFF_BH + (uint32_t)(wn * 32 * PITCH) + lanePart;
    const uint32_t bOffL = OFF_BL + (uint32_t)(wn * 32 * PITCH) + lanePart;

    float acc[2][4][4];
#pragma unroll
    for (int i = 0; i < 2; i++)
#pragma unroll
        for (int j = 0; j < 4; j++)
#pragma unroll
            for (int k = 0; k < 4; k++) acc[i][j][k] = 0.0f;

    const int NKT = L / BK;              // 64
    for (int kt = 0; kt < NKT; kt++) {
        CP_WAIT(2);
        __syncthreads();                 // single barrier per k-tile

        // stage (kt+3)%4 was read at iter kt-1 (ordered by the sync above)
        if (kt + 3 < NKT) load_stage((kt + 3) % STAGES, kt + 3);
        CP_COMMIT();

        const uint32_t sb = sbase + (kt % STAGES) * STAGE_B;
        uint32_t ah[2][4], al[2][4];
#pragma unroll
        for (int tm = 0; tm < 2; tm++) {
            ldsm4(ah[tm], sb + aOffH + (uint32_t)(tm * 16 * PITCH));
            if (USE_AL)
                ldsm4(al[tm], sb + aOffL + (uint32_t)(tm * 16 * PITCH));
        }
        uint32_t bh[4][2], bl[4][2];
#pragma unroll
        for (int g = 0; g < 2; g++) {
            uint32_t t[4];
            ldsm4(t, sb + bOffH + (uint32_t)(g * 16 * PITCH));
            bh[2 * g][0] = t[0];     bh[2 * g][1] = t[2];
            bh[2 * g + 1][0] = t[1]; bh[2 * g + 1][1] = t[3];
            if (USE_BL) {
                ldsm4(t, sb + bOffL + (uint32_t)(g * 16 * PITCH));
                bl[2 * g][0] = t[0];     bl[2 * g][1] = t[2];
                bl[2 * g + 1][0] = t[1]; bl[2 * g + 1][1] = t[3];
            }
        }
#pragma unroll
        for (int tm = 0; tm < 2; tm++)
#pragma unroll
            for (int tn = 0; tn < 4; tn++)
                mma16816(acc[tm][tn], ah[tm], bh[tn][0], bh[tn][1]);
        if (USE_BL) {
#pragma unroll
            for (int tm = 0; tm < 2; tm++)
#pragma unroll
                for (int tn = 0; tn < 4; tn++)
                    mma16816(acc[tm][tn], ah[tm], bl[tn][0], bl[tn][1]);
        }
        if (USE_AL) {
#pragma unroll
            for (int tm = 0; tm < 2; tm++)
#pragma unroll
                for (int tn = 0; tn < 4; tn++)
                    mma16816(acc[tm][tn], al[tm], bh[tn][0], bh[tn][1]);
        }
    }

    // ---- epilogue ----
    const int mBase = M0 + wm * 32 + (lane >> 2);
    const int cBase = N0 + wn * 32 + (lane & 3) * 2;
#pragma unroll
    for (int tm = 0; tm < 2; tm++)
#pragma unroll
        for (int tn = 0; tn < 4; tn++) {
            const float* a = acc[tm][tn];
            const int m = mBase + tm * 16;
            const int c = cBase + tn * 8;
            const size_t o0 = (size_t)m * L + c;
            const size_t o1 = o0 + 8 * L;
            if (EPI == 0) {
                *reinterpret_cast<float2*>(&outF[o0]) =
                    make_float2(a[0] * scale, a[1] * scale);
                *reinterpret_cast<float2*>(&outF[o1]) =
                    make_float2(a[2] * scale, a[3] * scale);
            } else {
#pragma unroll
                for (int p = 0; p < 2; p++) {
                    const float v0 = a[2 * p] * scale, v1 = a[2 * p + 1] * scale;
                    __half h0 = __float2half(v0);
                    __half h1 = __float2half(v1);
                    __half l0 = __float2half(v0 - __half2float(h0));
                    __half l1 = __float2half(v1 - __half2float(h1));
                    uint32_t hp = (uint32_t)__half_as_ushort(h0) |
                                  ((uint32_t)__half_as_ushort(h1) << 16);
                    uint32_t lp = (uint32_t)__half_as_ushort(l0) |
                                  ((uint32_t)__half_as_ushort(l1) << 16);
                    const size_t o = p ? o1 : o0;
                    *reinterpret_cast<uint32_t*>(&outHi[o]) = hp;
                    *reinterpret_cast<uint32_t*>(&outLo[o]) = lp;
                }
            }
        }
}

// ---------------------------------------------------------------------------
// kernels (grid: x = L/BN = 16, y = L/BM = 8, z = batch)
// ---------------------------------------------------------------------------
__global__ void __launch_bounds__(256, 3)
g_kernel(const __half* __restrict__ WKNH, const __half* __restrict__ WKNL,
         const __half* __restrict__ WQNH, const __half* __restrict__ WQNL,
         __half* __restrict__ GH, __half* __restrict__ GL)
{
    // G = wk.wq^T; inputs x256 each -> store G*16 -> scale 1/4096. 3-pass.
    gemm_core<1, true, true>(WKNH, WKNL, WQNH, WQNL, 1.0f / 4096.0f,
                             nullptr, GH, GL);
}

__global__ void __launch_bounds__(256, 3)
t_kernel(const __half* __restrict__ XTH, const __half* __restrict__ XTL,
         const __half* __restrict__ GH, const __half* __restrict__ GL,
         __half* __restrict__ TTH, __half* __restrict__ TTL)
{
    // tT = xT.G16 (stores 16*t). 3-pass.
    const size_t bo = (size_t)blockIdx.z * PER_B;
    gemm_core<1, true, true>(XTH + bo, XTL + bo, GH, GL, 1.0f,
                             nullptr, TTH + bo, TTL + bo);
}

__global__ void __launch_bounds__(256, 3)
kq_kernel(const __half* __restrict__ XTH, const __half* __restrict__ XTL,
          const __half* __restrict__ TTH, const __half* __restrict__ TTL,
          float* __restrict__ outF)
{
    // kq = xT.tT16 / 512 (= x.t/32). 3-pass, fp32 out.
    const size_t bo = (size_t)blockIdx.z * PER_B;
    gemm_core<0, true, true>(XTH + bo, XTL + bo, TTH + bo, TTL + bo,
                             1.0f / 512.0f, outF + bo, nullptr, nullptr);
}

__global__ void __launch_bounds__(256, 3)
u_kernel(const __half* __restrict__ SMH,
         const __half* __restrict__ XNH, const __half* __restrict__ XNL,
         __half* __restrict__ UH, __half* __restrict__ UL)
{
    // u = sm.xN (stores 256*u). 2-pass (sm 1-digit).
    const size_t bo = (size_t)blockIdx.z * PER_B;
    gemm_core<1, false, true>(SMH + bo, nullptr, XNH + bo, XNL + bo, 256.0f,
                              nullptr, UH + bo, UL + bo);
}

__global__ void __launch_bounds__(256, 3)
out_kernel(const __half* __restrict__ WVTH,
           const __half* __restrict__ UH, const __half* __restrict__ UL,
           float* __restrict__ outF)
{
    // out = wvT256.u256 / 65536. 2-pass (wv 1-digit).
    const size_t bo = (size_t)blockIdx.z * PER_B;
    gemm_core<0, false, true>(WVTH, nullptr, UH + bo, UL + bo,
                              1.0f / 65536.0f, outF + bo, nullptr, nullptr);
}

// ---------------------------------------------------------------------------
// Prep: z<16 -> x batch z: natural + transposed splits (prescale 1).
//       z=16 -> wk natural x256. z=17 -> wq natural x256. z=18 -> wv transp x256.
// ---------------------------------------------------------------------------
__global__ void __launch_bounds__(256)
prep_split(const float* __restrict__ x,
           const float* __restrict__ wk, const float* __restrict__ wq,
           const float* __restrict__ wv,
           __half* __restrict__ XTH, __half* __restrict__ XTL,
           __half* __restrict__ XNH, __half* __restrict__ XNL,
           __half* __restrict__ WKNH, __half* __restrict__ WKNL,
           __half* __restrict__ WQNH, __half* __restrict__ WQNL,
           __half* __restrict__ WVTH, __half* __restrict__ WVTL)
{
    __shared__ float t[32][33];
    const int z = blockIdx.z;
    const int tx = threadIdx.x, ty = threadIdx.y;
    const int r0 = blockIdx.y * 32, c0 = blockIdx.x * 32;

    const float* in;
    float pres = 1.0f;
    bool doNat = false, doTr = false;
    __half *nh = nullptr, *nl = nullptr, *th = nullptr, *tl = nullptr;

    if (z < 16) {
        in = x + (size_t)z * PER_B;
        doNat = true; doTr = true;
        nh = XNH + (size_t)z * PER_B; nl = XNL + (size_t)z * PER_B;
        th = XTH + (size_t)z * PER_B; tl = XTL + (size_t)z * PER_B;
    } else if (z == 16) {
        in = wk; pres = W_PRESCALE; doNat = true;
        nh = WKNH; nl = WKNL;
    } else if (z == 17) {
        in = wq; pres = W_PRESCALE; doNat = true;
        nh = WQNH; nl = WQNL;
    } else {
        in = wv; pres = W_PRESCALE; doTr = true;
        th = WVTH; tl = WVTL;
    }

    float v[4];
#pragma unroll
    for (int i = 0; i < 4; i++)
        v[i] = in[(size_t)(r0 + ty + i * 8) * L + c0 + tx] * pres;

    if (doNat) {
#pragma unroll
        for (int i = 0; i < 4; i++) {
            __half h = __float2half(v[i]);
            __half l = __float2half(v[i] - __half2float(h));
            size_t o = (size_t)(r0 + ty + i * 8) * L + c0 + tx;
            nh[o] = h;
            nl[o] = l;
        }
    }
    if (doTr) {
#pragma unroll
        for (int i = 0; i < 4; i++) t[ty + i * 8][tx] = v[i];
        __syncthreads();
#pragma unroll
        for (int i = 0; i < 4; i++) {
            float vv = t[tx][ty + i * 8];
            __half h = __float2half(vv);
            __half l = __float2half(vv - __half2float(h));
            size_t o = (size_t)(c0 + ty + i * 8) * L + r0 + tx;
            th[o] = h;
            tl[o] = l;
        }
    }
}

// ---------------------------------------------------------------------------
// row softmax (1024 wide), output single-digit fp16
// ---------------------------------------------------------------------------
__global__ void __launch_bounds__(256)
softmax_h(const float* __restrict__ kq, __half* __restrict__ oh)
{
    const size_t rb = (size_t)blockIdx.x * L;
    const int tid = threadIdx.x;
    float4 v = *reinterpret_cast<const float4*>(&kq[rb + tid * 4]);

    __shared__ float red[8];
    const int lane = tid & 31, wid = tid >> 5;

    float m = fmaxf(fmaxf(v.x, v.y), fmaxf(v.z, v.w));
#pragma unroll
    for (int o = 16; o; o >>= 1) m = fmaxf(m, __shfl_xor_sync(0xffffffffu, m, o));
    if (lane == 0) red[wid] = m;
    __syncthreads();
    m = red[0];
#pragma unroll
    for (int w = 1; w < 8; w++) m = fmaxf(m, red[w]);
    __syncthreads();

    v.x = expf(v.x - m); v.y = expf(v.y - m);
    v.z = expf(v.z - m); v.w = expf(v.w - m);
    float s = v.x + v.y + v.z + v.w;
#pragma unroll
    for (int o = 16; o; o >>= 1) s += __shfl_xor_sync(0xffffffffu, s, o);
    if (lane == 0) red[wid] = s;
    __syncthreads();
    s = red[0];
#pragma unroll
    for (int w = 1; w < 8; w++) s += red[w];

    const float inv = 1.0f / s;
    uint32_t p0 = (uint32_t)__half_as_ushort(__float2half(v.x * inv)) |
                  ((uint32_t)__half_as_ushort(__float2half(v.y * inv)) << 16);
    uint32_t p1 = (uint32_t)__half_as_ushort(__float2half(v.z * inv)) |
                  ((uint32_t)__half_as_ushort(__float2half(v.w * inv)) << 16);
    *reinterpret_cast<uint2*>(&oh[rb + tid * 4]) = make_uint2(p0, p1);
}

// ---------------------------------------------------------------------------
// host
// ---------------------------------------------------------------------------
extern "C" void kernel_launch(void* const* d_in, const int* in_sizes, int n_in,
                              void* d_out, int out_size)
{
    (void)in_sizes; (void)n_in; (void)out_size;
    const float* x  = (const float*)d_in[0];
    const float* wk = (const float*)d_in[1];
    const float* wq = (const float*)d_in[2];
    const float* wv = (const float*)d_in[3];
    float* out = (float*)d_out;

    void *xth, *xtl, *xnh, *xnl, *tth, *ttl, *smh, *uh, *ul;
    void *gh, *gl, *wknh, *wknl, *wqnh, *wqnl, *wvth, *wvtl, *kq;
    cudaGetSymbolAddress(&xth, g_xT_hi);  cudaGetSymbolAddress(&xtl, g_xT_lo);
    cudaGetSymbolAddress(&xnh, g_xN_hi);  cudaGetSymbolAddress(&xnl, g_xN_lo);
    cudaGetSymbolAddress(&tth, g_tT_hi);  cudaGetSymbolAddress(&ttl, g_tT_lo);
    cudaGetSymbolAddress(&smh, g_sm_hi);
    cudaGetSymbolAddress(&uh, g_u_hi);    cudaGetSymbolAddress(&ul, g_u_lo);
    cudaGetSymbolAddress(&gh, g_G_hi);    cudaGetSymbolAddress(&gl, g_G_lo);
    cudaGetSymbolAddress(&wknh, g_wkN_hi); cudaGetSymbolAddress(&wknl, g_wkN_lo);
    cudaGetSymbolAddress(&wqnh, g_wqN_hi); cudaGetSymbolAddress(&wqnl, g_wqN_lo);
    cudaGetSymbolAddress(&wvth, g_wvT_hi); cudaGetSymbolAddress(&wvtl, g_wvT_lo);
    cudaGetSymbolAddress(&kq, g_kq);

    cudaFuncSetAttribute((const void*)g_kernel,
                         cudaFuncAttributeMaxDynamicSharedMemorySize, SMEM_DYN);
    cudaFuncSetAttribute((const void*)t_kernel,
                         cudaFuncAttributeMaxDynamicSharedMemorySize, SMEM_DYN);
    cudaFuncSetAttribute((const void*)kq_kernel,
                         cudaFuncAttributeMaxDynamicSharedMemorySize, SMEM_DYN);
    cudaFuncSetAttribute((const void*)u_kernel,
                         cudaFuncAttributeMaxDynamicSharedMemorySize, SMEM_DYN);
    cudaFuncSetAttribute((const void*)out_kernel,
                         cudaFuncAttributeMaxDynamicSharedMemorySize, SMEM_DYN);

    // prep: x -> XT + XN (16 z's); wk,wq natural; wv transposed
    prep_split<<<dim3(32, 32, 19), dim3(32, 8)>>>(
        x, wk, wq, wv,
        (__half*)xth, (__half*)xtl, (__half*)xnh, (__half*)xnl,
        (__half*)wknh, (__half*)wknl, (__half*)wqnh, (__half*)wqnl,
        (__half*)wvth, (__half*)wvtl);

    const dim3 gg(L / BN, L / BM, BATCH);     // 16 x 8 x 16

    // G = wk.wq^T (unbatched)
    g_kernel<<<dim3(L / BN, L / BM, 1), 256, SMEM_DYN>>>(
        (__half*)wknh, (__half*)wknl, (__half*)wqnh, (__half*)wqnl,
        (__half*)gh, (__half*)gl);

    // tT = xT . G
    t_kernel<<<gg, 256, SMEM_DYN>>>(
        (__half*)xth, (__half*)xtl, (__half*)gh, (__half*)gl,
        (__half*)tth, (__half*)ttl);

    // kq = xT . tT / 32
    kq_kernel<<<gg, 256, SMEM_DYN>>>(
        (__half*)xth, (__half*)xtl, (__half*)tth, (__half*)ttl, (float*)kq);

    // softmax -> sm (1 digit)
    softmax_h<<<BATCH * L, 256>>>((const float*)kq, (__half*)smh);

    // u = sm . xN
    u_kernel<<<gg, 256, SMEM_DYN>>>(
        (__half*)smh, (__half*)xnh, (__half*)xnl, (__half*)uh, (__half*)ul);

    // out = wvT . u
    out_kernel<<<gg, 256, SMEM_DYN>>>(
        (__half*)wvth, (__half*)uh, (__half*)ul, out);
}

// round 9
// speedup vs baseline: 2.8824x; 1.0414x over previous
#include <cuda_runtime.h>
#include <cuda_fp16.h>
#include <cstdint>
#include <cstddef>

// ===========================================================================
// SelfAttention via mma.sync.m16n8k16 (fp16 digits, fp32 acc), split-fp16
// multi-pass fp32 emulation, restructured algebra:
//   G  = wk . wq^T   (unbatched, 3-pass)
//   tT = xT . G      (batched, 3-pass)
//   kq = xT . tT /32 (batched, 3-pass)
//   sm = softmax(kq)
//   u  = sm . xN     (batched, 2-pass)
//   out= wvT . u     (batched, 2-pass)
// GEMM core: 128x128 CTA tile, 256 threads (4Mx2N warps, 32x64 warp tile),
// BK=16, 4-stage cp.async, one barrier per k-tile, 96KB smem -> 2 CTAs/SM.
// Pass order (hh, al*bh, ah*bl) lets bh die before bl loads: fewer live regs.
// ===========================================================================

#define L 1024
#define BATCH 16
#define PER_B ((size_t)L * L)
#define ELTS ((size_t)BATCH * L * L)

#define BM 128
#define BN 128
#define BK 16
#define STAGES 4
#define PITCH 48                         // 32B data + 16B pad per 16-fp16 row
#define A_COMP (128 * PITCH)             // 6144 B
#define OFF_AH 0
#define OFF_AL (A_COMP)                  // 6144
#define OFF_BH (2 * A_COMP)              // 12288
#define OFF_BL (3 * A_COMP)              // 18432
#define STAGE_B (4 * A_COMP)             // 24576
#define SMEM_DYN (STAGES * STAGE_B)      // 98304

#define W_PRESCALE 256.0f

// ---- scratch (device globals; cudaMalloc forbidden) ----
__device__ __align__(1024) __half g_xT_hi[ELTS], g_xT_lo[ELTS];   // x transposed
__device__ __align__(1024) __half g_xN_hi[ELTS], g_xN_lo[ELTS];   // x natural
__device__ __align__(1024) __half g_tT_hi[ELTS], g_tT_lo[ELTS];   // (xT.G) * 16
__device__ __align__(1024) __half g_sm_hi[ELTS];                  // softmax, 1 digit
__device__ __align__(1024) __half g_u_hi[ELTS],  g_u_lo[ELTS];    // (sm.xN) * 256
__device__ __align__(1024) __half g_G_hi[L * L], g_G_lo[L * L];   // wk.wq^T * 16
__device__ __align__(1024) __half g_wkN_hi[L * L], g_wkN_lo[L * L];  // *256
__device__ __align__(1024) __half g_wqN_hi[L * L], g_wqN_lo[L * L];  // *256
__device__ __align__(1024) __half g_wvT_hi[L * L], g_wvT_lo[L * L];  // *256
__device__ __align__(1024) float g_kq[ELTS];

// ---------------------------------------------------------------------------
__device__ __forceinline__ uint32_t smem_u32(const void* p) {
    uint32_t a;
    asm("{ .reg .u64 t; cvta.to.shared.u64 t, %1; cvt.u32.u64 %0, t; }"
        : "=r"(a) : "l"(p));
    return a;
}

__device__ __forceinline__ void cp16(uint32_t dst, const void* src) {
    asm volatile("cp.async.cg.shared.global [%0], [%1], 16;"
                 :: "r"(dst), "l"(src) : "memory");
}
#define CP_COMMIT() asm volatile("cp.async.commit_group;" ::: "memory")
#define CP_WAIT(n)  asm volatile("cp.async.wait_group %0;" :: "n"(n) : "memory")

__device__ __forceinline__ void ldsm4(uint32_t* r, uint32_t addr) {
    asm volatile("ldmatrix.sync.aligned.m8n8.x4.shared.b16 {%0,%1,%2,%3}, [%4];"
                 : "=r"(r[0]), "=r"(r[1]), "=r"(r[2]), "=r"(r[3]) : "r"(addr));
}

__device__ __forceinline__ void mma16816(float* d, const uint32_t* a,
                                         uint32_t b0, uint32_t b1) {
    asm volatile(
        "mma.sync.aligned.m16n8k16.row.col.f32.f16.f16.f32 "
        "{%0,%1,%2,%3}, {%4,%5,%6,%7}, {%8,%9}, {%0,%1,%2,%3};"
        : "+f"(d[0]), "+f"(d[1]), "+f"(d[2]), "+f"(d[3])
        : "r"(a[0]), "r"(a[1]), "r"(a[2]), "r"(a[3]), "r"(b0), "r"(b1));
}

// ---------------------------------------------------------------------------
// Core GEMM: D[i][j] = sum_k A[i][k]*B[j][k] for one 1024x1024 problem.
// 256 threads: 4(M) x 2(N) warps, 32x64 warp tiles, CTA tile 128x128, BK=16.
// Passes: Ah*Bh always; Al*Bh if USE_AL; Ah*Bl if USE_BL.
// EPI==0: fp32*scale to outF.  EPI==1: hi/lo fp16 split of acc*scale.
// ---------------------------------------------------------------------------
template <int EPI, bool USE_AL, bool USE_BL>
__device__ __forceinline__ void gemm_core(
    const __half* __restrict__ Ah, const __half* __restrict__ Al,
    const __half* __restrict__ Bh, const __half* __restrict__ Bl,
    float scale, float* __restrict__ outF,
    __half* __restrict__ outHi, __half* __restrict__ outLo)
{
    extern __shared__ char dyn[];
    const uint32_t sbase = smem_u32(dyn);

    const int tid  = threadIdx.x;
    const int wid  = tid >> 5;
    const int lane = tid & 31;
    const int wm   = wid & 3;            // 4 warps along M (32 rows)
    const int wn   = wid >> 2;           // 2 warps along N (64 cols)

    const int M0 = blockIdx.y * BM;
    const int N0 = blockIdx.x * BN;

    // ---- cp.async mapping: ci = tid&1 (16B chunk), rr = tid>>1 (row 0..127)
    // each thread loads Ah[rr], (Al[rr]), Bh[rr], (Bl[rr]) at chunk ci
    const int ci = tid & 1;
    const int rr = tid >> 1;
    const __half* gAh = Ah + (size_t)(M0 + rr) * L;
    const __half* gAl = USE_AL ? (Al + (size_t)(M0 + rr) * L) : nullptr;
    const __half* gBh = Bh + (size_t)(N0 + rr) * L;
    const __half* gBl = USE_BL ? (Bl + (size_t)(N0 + rr) * L) : nullptr;
    const uint32_t sOff = rr * PITCH + ci * 16;

    auto load_stage = [&](int stage, int kt) {
        const uint32_t sb = sbase + stage * STAGE_B;
        const size_t   gk = (size_t)kt * BK + ci * 8;
        cp16(sb + OFF_AH + sOff, gAh + gk);
        if (USE_AL) cp16(sb + OFF_AL + sOff, gAl + gk);
        cp16(sb + OFF_BH + sOff, gBh + gk);
        if (USE_BL) cp16(sb + OFF_BL + sOff, gBl + gk);
    };

    load_stage(0, 0); CP_COMMIT();
    load_stage(1, 1); CP_COMMIT();
    load_stage(2, 2); CP_COMMIT();

    const uint32_t lanePart = (uint32_t)((lane & 15) * PITCH + (lane >> 4) * 16);
    const uint32_t aOffH = OFF_AH + (uint32_t)(wm * 32 * PITCH) + lanePart;
    const uint32_t aOffL = OFF_AL + (uint32_t)(wm * 32 * PITCH) + lanePart;
    const uint32_t bOffH = OFF_BH + (uint32_t)(wn * 64 * PITCH) + lanePart;
    const uint32_t bOffL = OFF_BL + (uint32_t)(wn * 64 * PITCH) + lanePart;

    float acc[2][8][4];
#pragma unroll
    for (int i = 0; i < 2; i++)
#pragma unroll
        for (int j = 0; j < 8; j++)
#pragma unroll
            for (int k = 0; k < 4; k++) acc[i][j][k] = 0.0f;

    const int NKT = L / BK;              // 64
    for (int kt = 0; kt < NKT; kt++) {
        CP_WAIT(2);
        __syncthreads();                 // single barrier per k-tile

        // stage (kt+3)%4 was read at iter kt-1 (ordered by the sync above)
        if (kt + 3 < NKT) load_stage((kt + 3) % STAGES, kt + 3);
        CP_COMMIT();

        const uint32_t sb = sbase + (kt % STAGES) * STAGE_B;

        uint32_t ah[2][4], al[2][4];
#pragma unroll
        for (int tm = 0; tm < 2; tm++) {
            ldsm4(ah[tm], sb + aOffH + (uint32_t)(tm * 16 * PITCH));
            if (USE_AL)
                ldsm4(al[tm], sb + aOffL + (uint32_t)(tm * 16 * PITCH));
        }
        // B hi fragments: 64 cols = 8 n8 frags via 4 ldsm.x4
        uint32_t bh[8][2];
#pragma unroll
        for (int g = 0; g < 4; g++) {
            uint32_t t[4];
            ldsm4(t, sb + bOffH + (uint32_t)(g * 16 * PITCH));
            bh[2 * g][0] = t[0];     bh[2 * g][1] = t[2];
            bh[2 * g + 1][0] = t[1]; bh[2 * g + 1][1] = t[3];
        }
        // pass 1: ah * bh
#pragma unroll
        for (int tm = 0; tm < 2; tm++)
#pragma unroll
            for (int tn = 0; tn < 8; tn++)
                mma16816(acc[tm][tn], ah[tm], bh[tn][0], bh[tn][1]);
        // pass 2: al * bh  (bh dies after this)
        if (USE_AL) {
#pragma unroll
            for (int tm = 0; tm < 2; tm++)
#pragma unroll
                for (int tn = 0; tn < 8; tn++)
                    mma16816(acc[tm][tn], al[tm], bh[tn][0], bh[tn][1]);
        }
        // pass 3: ah * bl  (bl loaded after bh is dead)
        if (USE_BL) {
            uint32_t bl[8][2];
#pragma unroll
            for (int g = 0; g < 4; g++) {
                uint32_t t[4];
                ldsm4(t, sb + bOffL + (uint32_t)(g * 16 * PITCH));
                bl[2 * g][0] = t[0];     bl[2 * g][1] = t[2];
                bl[2 * g + 1][0] = t[1]; bl[2 * g + 1][1] = t[3];
            }
#pragma unroll
            for (int tm = 0; tm < 2; tm++)
#pragma unroll
                for (int tn = 0; tn < 8; tn++)
                    mma16816(acc[tm][tn], ah[tm], bl[tn][0], bl[tn][1]);
        }
    }

    // ---- epilogue ----
    const int mBase = M0 + wm * 32 + (lane >> 2);
    const int cBase = N0 + wn * 64 + (lane & 3) * 2;
#pragma unroll
    for (int tm = 0; tm < 2; tm++)
#pragma unroll
        for (int tn = 0; tn < 8; tn++) {
            const float* a = acc[tm][tn];
            const int m = mBase + tm * 16;
            const int c = cBase + tn * 8;
            const size_t o0 = (size_t)m * L + c;
            const size_t o1 = o0 + 8 * L;
            if (EPI == 0) {
                *reinterpret_cast<float2*>(&outF[o0]) =
                    make_float2(a[0] * scale, a[1] * scale);
                *reinterpret_cast<float2*>(&outF[o1]) =
                    make_float2(a[2] * scale, a[3] * scale);
            } else {
#pragma unroll
                for (int p = 0; p < 2; p++) {
                    const float v0 = a[2 * p] * scale, v1 = a[2 * p + 1] * scale;
                    __half h0 = __float2half(v0);
                    __half h1 = __float2half(v1);
                    __half l0 = __float2half(v0 - __half2float(h0));
                    __half l1 = __float2half(v1 - __half2float(h1));
                    uint32_t hp = (uint32_t)__half_as_ushort(h0) |
                                  ((uint32_t)__half_as_ushort(h1) << 16);
                    uint32_t lp = (uint32_t)__half_as_ushort(l0) |
                                  ((uint32_t)__half_as_ushort(l1) << 16);
                    const size_t o = p ? o1 : o0;
                    *reinterpret_cast<uint32_t*>(&outHi[o]) = hp;
                    *reinterpret_cast<uint32_t*>(&outLo[o]) = lp;
                }
            }
        }
}

// ---------------------------------------------------------------------------
// kernels (grid: x = L/BN = 8, y = L/BM = 8, z = batch)
// ---------------------------------------------------------------------------
__global__ void __launch_bounds__(256, 2)
g_kernel(const __half* __restrict__ WKNH, const __half* __restrict__ WKNL,
         const __half* __restrict__ WQNH, const __half* __restrict__ WQNL,
         __half* __restrict__ GH, __half* __restrict__ GL)
{
    // G = wk.wq^T; inputs x256 each -> store G*16 -> scale 1/4096. 3-pass.
    gemm_core<1, true, true>(WKNH, WKNL, WQNH, WQNL, 1.0f / 4096.0f,
                             nullptr, GH, GL);
}

__global__ void __launch_bounds__(256, 2)
t_kernel(const __half* __restrict__ XTH, const __half* __restrict__ XTL,
         const __half* __restrict__ GH, const __half* __restrict__ GL,
         __half* __restrict__ TTH, __half* __restrict__ TTL)
{
    // tT = xT.G16 (stores 16*t). 3-pass.
    const size_t bo = (size_t)blockIdx.z * PER_B;
    gemm_core<1, true, true>(XTH + bo, XTL + bo, GH, GL, 1.0f,
                             nullptr, TTH + bo, TTL + bo);
}

__global__ void __launch_bounds__(256, 2)
kq_kernel(const __half* __restrict__ XTH, const __half* __restrict__ XTL,
          const __half* __restrict__ TTH, const __half* __restrict__ TTL,
          float* __restrict__ outF)
{
    // kq = xT.tT16 / 512 (= x.t/32). 3-pass, fp32 out.
    const size_t bo = (size_t)blockIdx.z * PER_B;
    gemm_core<0, true, true>(XTH + bo, XTL + bo, TTH + bo, TTL + bo,
                             1.0f / 512.0f, outF + bo, nullptr, nullptr);
}

__global__ void __launch_bounds__(256, 2)
u_kernel(const __half* __restrict__ SMH,
         const __half* __restrict__ XNH, const __half* __restrict__ XNL,
         __half* __restrict__ UH, __half* __restrict__ UL)
{
    // u = sm.xN (stores 256*u). 2-pass (sm 1-digit).
    const size_t bo = (size_t)blockIdx.z * PER_B;
    gemm_core<1, false, true>(SMH + bo, nullptr, XNH + bo, XNL + bo, 256.0f,
                              nullptr, UH + bo, UL + bo);
}

__global__ void __launch_bounds__(256, 2)
out_kernel(const __half* __restrict__ WVTH,
           const __half* __restrict__ UH, const __half* __restrict__ UL,
           float* __restrict__ outF)
{
    // out = wvT256.u256 / 65536. 2-pass (wv 1-digit).
    const size_t bo = (size_t)blockIdx.z * PER_B;
    gemm_core<0, false, true>(WVTH, nullptr, UH + bo, UL + bo,
                              1.0f / 65536.0f, outF + bo, nullptr, nullptr);
}

// ---------------------------------------------------------------------------
// Prep: z<16 -> x batch z: natural + transposed splits (prescale 1).
//       z=16 -> wk natural x256. z=17 -> wq natural x256. z=18 -> wv transp x256.
// ---------------------------------------------------------------------------
__global__ void __launch_bounds__(256)
prep_split(const float* __restrict__ x,
           const float* __restrict__ wk, const float* __restrict__ wq,
           const float* __restrict__ wv,
           __half* __restrict__ XTH, __half* __restrict__ XTL,
           __half* __restrict__ XNH, __half* __restrict__ XNL,
           __half* __restrict__ WKNH, __half* __restrict__ WKNL,
           __half* __restrict__ WQNH, __half* __restrict__ WQNL,
           __half* __restrict__ WVTH, __half* __restrict__ WVTL)
{
    __shared__ float t[32][33];
    const int z = blockIdx.z;
    const int tx = threadIdx.x, ty = threadIdx.y;
    const int r0 = blockIdx.y * 32, c0 = blockIdx.x * 32;

    const float* in;
    float pres = 1.0f;
    bool doNat = false, doTr = false;
    __half *nh = nullptr, *nl = nullptr, *th = nullptr, *tl = nullptr;

    if (z < 16) {
        in = x + (size_t)z * PER_B;
        doNat = true; doTr = true;
        nh = XNH + (size_t)z * PER_B; nl = XNL + (size_t)z * PER_B;
        th = XTH + (size_t)z * PER_B; tl = XTL + (size_t)z * PER_B;
    } else if (z == 16) {
        in = wk; pres = W_PRESCALE; doNat = true;
        nh = WKNH; nl = WKNL;
    } else if (z == 17) {
        in = wq; pres = W_PRESCALE; doNat = true;
        nh = WQNH; nl = WQNL;
    } else {
        in = wv; pres = W_PRESCALE; doTr = true;
        th = WVTH; tl = WVTL;
    }

    float v[4];
#pragma unroll
    for (int i = 0; i < 4; i++)
        v[i] = in[(size_t)(r0 + ty + i * 8) * L + c0 + tx] * pres;

    if (doNat) {
#pragma unroll
        for (int i = 0; i < 4; i++) {
            __half h = __float2half(v[i]);
            __half l = __float2half(v[i] - __half2float(h));
            size_t o = (size_t)(r0 + ty + i * 8) * L + c0 + tx;
            nh[o] = h;
            nl[o] = l;
        }
    }
    if (doTr) {
#pragma unroll
        for (int i = 0; i < 4; i++) t[ty + i * 8][tx] = v[i];
        __syncthreads();
#pragma unroll
        for (int i = 0; i < 4; i++) {
            float vv = t[tx][ty + i * 8];
            __half h = __float2half(vv);
            __half l = __float2half(vv - __half2float(h));
            size_t o = (size_t)(c0 + ty + i * 8) * L + r0 + tx;
            th[o] = h;
            tl[o] = l;
        }
    }
}

// ---------------------------------------------------------------------------
// row softmax (1024 wide), output single-digit fp16
// ---------------------------------------------------------------------------
__global__ void __launch_bounds__(256)
softmax_h(const float* __restrict__ kq, __half* __restrict__ oh)
{
    const size_t rb = (size_t)blockIdx.x * L;
    const int tid = threadIdx.x;
    float4 v = *reinterpret_cast<const float4*>(&kq[rb + tid * 4]);

    __shared__ float red[8];
    const int lane = tid & 31, wid = tid >> 5;

    float m = fmaxf(fmaxf(v.x, v.y), fmaxf(v.z, v.w));
#pragma unroll
    for (int o = 16; o; o >>= 1) m = fmaxf(m, __shfl_xor_sync(0xffffffffu, m, o));
    if (lane == 0) red[wid] = m;
    __syncthreads();
    m = red[0];
#pragma unroll
    for (int w = 1; w < 8; w++) m = fmaxf(m, red[w]);
    __syncthreads();

    v.x = expf(v.x - m); v.y = expf(v.y - m);
    v.z = expf(v.z - m); v.w = expf(v.w - m);
    float s = v.x + v.y + v.z + v.w;
#pragma unroll
    for (int o = 16; o; o >>= 1) s += __shfl_xor_sync(0xffffffffu, s, o);
    if (lane == 0) red[wid] = s;
    __syncthreads();
    s = red[0];
#pragma unroll
    for (int w = 1; w < 8; w++) s += red[w];

    const float inv = 1.0f / s;
    uint32_t p0 = (uint32_t)__half_as_ushort(__float2half(v.x * inv)) |
                  ((uint32_t)__half_as_ushort(__float2half(v.y * inv)) << 16);
    uint32_t p1 = (uint32_t)__half_as_ushort(__float2half(v.z * inv)) |
                  ((uint32_t)__half_as_ushort(__float2half(v.w * inv)) << 16);
    *reinterpret_cast<uint2*>(&oh[rb + tid * 4]) = make_uint2(p0, p1);
}

// ---------------------------------------------------------------------------
// host
// ---------------------------------------------------------------------------
extern "C" void kernel_launch(void* const* d_in, const int* in_sizes, int n_in,
                              void* d_out, int out_size)
{
    (void)in_sizes; (void)n_in; (void)out_size;
    const float* x  = (const float*)d_in[0];
    const float* wk = (const float*)d_in[1];
    const float* wq = (const float*)d_in[2];
    const float* wv = (const float*)d_in[3];
    float* out = (float*)d_out;

    void *xth, *xtl, *xnh, *xnl, *tth, *ttl, *smh, *uh, *ul;
    void *gh, *gl, *wknh, *wknl, *wqnh, *wqnl, *wvth, *wvtl, *kq;
    cudaGetSymbolAddress(&xth, g_xT_hi);  cudaGetSymbolAddress(&xtl, g_xT_lo);
    cudaGetSymbolAddress(&xnh, g_xN_hi);  cudaGetSymbolAddress(&xnl, g_xN_lo);
    cudaGetSymbolAddress(&tth, g_tT_hi);  cudaGetSymbolAddress(&ttl, g_tT_lo);
    cudaGetSymbolAddress(&smh, g_sm_hi);
    cudaGetSymbolAddress(&uh, g_u_hi);    cudaGetSymbolAddress(&ul, g_u_lo);
    cudaGetSymbolAddress(&gh, g_G_hi);    cudaGetSymbolAddress(&gl, g_G_lo);
    cudaGetSymbolAddress(&wknh, g_wkN_hi); cudaGetSymbolAddress(&wknl, g_wkN_lo);
    cudaGetSymbolAddress(&wqnh, g_wqN_hi); cudaGetSymbolAddress(&wqnl, g_wqN_lo);
    cudaGetSymbolAddress(&wvth, g_wvT_hi); cudaGetSymbolAddress(&wvtl, g_wvT_lo);
    cudaGetSymbolAddress(&kq, g_kq);

    cudaFuncSetAttribute((const void*)g_kernel,
                         cudaFuncAttributeMaxDynamicSharedMemorySize, SMEM_DYN);
    cudaFuncSetAttribute((const void*)t_kernel,
                         cudaFuncAttributeMaxDynamicSharedMemorySize, SMEM_DYN);
    cudaFuncSetAttribute((const void*)kq_kernel,
                         cudaFuncAttributeMaxDynamicSharedMemorySize, SMEM_DYN);
    cudaFuncSetAttribute((const void*)u_kernel,
                         cudaFuncAttributeMaxDynamicSharedMemorySize, SMEM_DYN);
    cudaFuncSetAttribute((const void*)out_kernel,
                         cudaFuncAttributeMaxDynamicSharedMemorySize, SMEM_DYN);

    // prep: x -> XT + XN (16 z's); wk,wq natural; wv transposed
    prep_split<<<dim3(32, 32, 19), dim3(32, 8)>>>(
        x, wk, wq, wv,
        (__half*)xth, (__half*)xtl, (__half*)xnh, (__half*)xnl,
        (__half*)wknh, (__half*)wknl, (__half*)wqnh, (__half*)wqnl,
        (__half*)wvth, (__half*)wvtl);

    const dim3 gg(L / BN, L / BM, BATCH);     // 8 x 8 x 16

    // G = wk.wq^T (unbatched)
    g_kernel<<<dim3(L / BN, L / BM, 1), 256, SMEM_DYN>>>(
        (__half*)wknh, (__half*)wknl, (__half*)wqnh, (__half*)wqnl,
        (__half*)gh, (__half*)gl);

    // tT = xT . G
    t_kernel<<<gg, 256, SMEM_DYN>>>(
        (__half*)xth, (__half*)xtl, (__half*)gh, (__half*)gl,
        (__half*)tth, (__half*)ttl);

    // kq = xT . tT / 32
    kq_kernel<<<gg, 256, SMEM_DYN>>>(
        (__half*)xth, (__half*)xtl, (__half*)tth, (__half*)ttl, (float*)kq);

    // softmax -> sm (1 digit)
    softmax_h<<<BATCH * L, 256>>>((const float*)kq, (__half*)smh);

    // u = sm . xN
    u_kernel<<<gg, 256, SMEM_DYN>>>(
        (__half*)smh, (__half*)xnh, (__half*)xnl, (__half*)uh, (__half*)ul);

    // out = wvT . u
    out_kernel<<<gg, 256, SMEM_DYN>>>(
        (__half*)wvth, (__half*)uh, (__half*)ul, out);
}

// round 10
// speedup vs baseline: 3.4997x; 1.2142x over previous
#include <cuda_runtime.h>
#include <cuda_fp16.h>
#include <cstdint>
#include <cstddef>

// ===========================================================================
// SelfAttention via mma.sync.m16n8k16 (fp16 digits, fp32 acc), split-fp16
// multi-pass fp32 emulation, restructured algebra:
//   G  = wk . wq^T   (unbatched, 3-pass)
//   tT = xT . G      (batched, 3-pass)
//   kq = xT . tT /32 (batched, 3-pass)
//   sm = softmax(kq) (1-digit)
//   u  = sm . xN     (batched, 1-pass, x 1-digit, u stored 1-digit)
//   out= wvT . u     (batched, 1-pass)
// GEMM core: 128x128 CTA tile, 256 threads (4Mx2N warps, 32x64 warp tile),
// BK=32 (2 k16-steps), 2-stage cp.async double buffer, 80KB smem ->
// 2 CTAs/SM. Halves the barrier-aligned ldsm phases vs BK=16.
// ===========================================================================

#define L 1024
#define BATCH 16
#define PER_B ((size_t)L * L)
#define ELTS ((size_t)BATCH * L * L)

#define BM 128
#define BN 128
#define BK 32
#define STAGES 2
#define PITCH 80                         // 64B data + 16B pad per 32-fp16 row
#define A_COMP (128 * PITCH)             // 10240 B
#define OFF_AH 0
#define OFF_AL (A_COMP)
#define OFF_BH (2 * A_COMP)
#define OFF_BL (3 * A_COMP)
#define STAGE_B (4 * A_COMP)             // 40960 B
#define SMEM_DYN (STAGES * STAGE_B)      // 81920 B

#define W_PRESCALE 256.0f

// ---- scratch (device globals; cudaMalloc forbidden) ----
__device__ __align__(1024) __half g_xT_hi[ELTS], g_xT_lo[ELTS];   // x transposed
__device__ __align__(1024) __half g_xN_hi[ELTS];                  // x natural, 1 digit
__device__ __align__(1024) __half g_tT_hi[ELTS], g_tT_lo[ELTS];   // (xT.G) * 16
__device__ __align__(1024) __half g_sm_hi[ELTS];                  // softmax, 1 digit
__device__ __align__(1024) __half g_u_hi[ELTS];                   // (sm.xN)*256, 1 digit
__device__ __align__(1024) __half g_G_hi[L * L], g_G_lo[L * L];   // wk.wq^T * 16
__device__ __align__(1024) __half g_wkN_hi[L * L], g_wkN_lo[L * L];  // *256
__device__ __align__(1024) __half g_wqN_hi[L * L], g_wqN_lo[L * L];  // *256
__device__ __align__(1024) __half g_wvT_hi[L * L];                   // *256, 1 digit
__device__ __align__(1024) float g_kq[ELTS];

// ---------------------------------------------------------------------------
__device__ __forceinline__ uint32_t smem_u32(const void* p) {
    uint32_t a;
    asm("{ .reg .u64 t; cvta.to.shared.u64 t, %1; cvt.u32.u64 %0, t; }"
        : "=r"(a) : "l"(p));
    return a;
}

__device__ __forceinline__ void cp16(uint32_t dst, const void* src) {
    asm volatile("cp.async.cg.shared.global [%0], [%1], 16;"
                 :: "r"(dst), "l"(src) : "memory");
}
#define CP_COMMIT() asm volatile("cp.async.commit_group;" ::: "memory")
#define CP_WAIT(n)  asm volatile("cp.async.wait_group %0;" :: "n"(n) : "memory")

__device__ __forceinline__ void ldsm4(uint32_t* r, uint32_t addr) {
    asm volatile("ldmatrix.sync.aligned.m8n8.x4.shared.b16 {%0,%1,%2,%3}, [%4];"
                 : "=r"(r[0]), "=r"(r[1]), "=r"(r[2]), "=r"(r[3]) : "r"(addr));
}

__device__ __forceinline__ void mma16816(float* d, const uint32_t* a,
                                         uint32_t b0, uint32_t b1) {
    asm volatile(
        "mma.sync.aligned.m16n8k16.row.col.f32.f16.f16.f32 "
        "{%0,%1,%2,%3}, {%4,%5,%6,%7}, {%8,%9}, {%0,%1,%2,%3};"
        : "+f"(d[0]), "+f"(d[1]), "+f"(d[2]), "+f"(d[3])
        : "r"(a[0]), "r"(a[1]), "r"(a[2]), "r"(a[3]), "r"(b0), "r"(b1));
}

// ---------------------------------------------------------------------------
// Core GEMM: D[i][j] = sum_k A[i][k]*B[j][k] for one 1024x1024 problem.
// 256 threads: 4(M) x 2(N) warps, 32x64 warp tiles, CTA 128x128, BK=32.
// Passes per k16-step: Ah*Bh always; Al*Bh if USE_AL; Ah*Bl if USE_BL.
// EPI 0: fp32*scale.  EPI 1: hi/lo fp16 split.  EPI 2: hi fp16 only.
// ---------------------------------------------------------------------------
template <int EPI, bool USE_AL, bool USE_BL>
__device__ __forceinline__ void gemm_core(
    const __half* __restrict__ Ah, const __half* __restrict__ Al,
    const __half* __restrict__ Bh, const __half* __restrict__ Bl,
    float scale, float* __restrict__ outF,
    __half* __restrict__ outHi, __half* __restrict__ outLo)
{
    extern __shared__ char dyn[];
    const uint32_t sbase = smem_u32(dyn);

    const int tid  = threadIdx.x;
    const int wid  = tid >> 5;
    const int lane = tid & 31;
    const int wm   = wid & 3;            // 4 warps along M (32 rows)
    const int wn   = wid >> 2;           // 2 warps along N (64 cols)

    const int M0 = blockIdx.y * BM;
    const int N0 = blockIdx.x * BN;

    // ---- cp.async: ci = tid&3 (16B chunk of 64B row), rr = tid>>2 (0..63)
    // each thread loads rows rr and rr+64 of each active component
    const int ci = tid & 3;
    const int rr = tid >> 2;
    const __half* gAh = Ah + (size_t)(M0 + rr) * L;
    const __half* gAl = USE_AL ? (Al + (size_t)(M0 + rr) * L) : nullptr;
    const __half* gBh = Bh + (size_t)(N0 + rr) * L;
    const __half* gBl = USE_BL ? (Bl + (size_t)(N0 + rr) * L) : nullptr;
    const uint32_t sOff  = rr * PITCH + ci * 16;
    const uint32_t sOff2 = (rr + 64) * PITCH + ci * 16;
    const size_t g2 = (size_t)64 * L;

    auto load_stage = [&](int stage, int kt) {
        const uint32_t sb = sbase + stage * STAGE_B;
        const size_t   gk = (size_t)kt * BK + ci * 8;
        cp16(sb + OFF_AH + sOff,  gAh + gk);
        cp16(sb + OFF_AH + sOff2, gAh + g2 + gk);
        if (USE_AL) {
            cp16(sb + OFF_AL + sOff,  gAl + gk);
            cp16(sb + OFF_AL + sOff2, gAl + g2 + gk);
        }
        cp16(sb + OFF_BH + sOff,  gBh + gk);
        cp16(sb + OFF_BH + sOff2, gBh + g2 + gk);
        if (USE_BL) {
            cp16(sb + OFF_BL + sOff,  gBl + gk);
            cp16(sb + OFF_BL + sOff2, gBl + g2 + gk);
        }
    };

    load_stage(0, 0); CP_COMMIT();
    load_stage(1, 1); CP_COMMIT();

    const uint32_t lanePart = (uint32_t)((lane & 15) * PITCH + (lane >> 4) * 16);
    const uint32_t aOffH = OFF_AH + (uint32_t)(wm * 32 * PITCH) + lanePart;
    const uint32_t aOffL = OFF_AL + (uint32_t)(wm * 32 * PITCH) + lanePart;
    const uint32_t bOffH = OFF_BH + (uint32_t)(wn * 64 * PITCH) + lanePart;
    const uint32_t bOffL = OFF_BL + (uint32_t)(wn * 64 * PITCH) + lanePart;

    float acc[2][8][4];
#pragma unroll
    for (int i = 0; i < 2; i++)
#pragma unroll
        for (int j = 0; j < 8; j++)
#pragma unroll
            for (int k = 0; k < 4; k++) acc[i][j][k] = 0.0f;

    const int NKT = L / BK;              // 32
    for (int kt = 0; kt < NKT; kt++) {
        CP_WAIT(1);
        __syncthreads();                 // stage kt&1 is full

        const uint32_t sb = sbase + (kt & 1) * STAGE_B;
#pragma unroll
        for (int ks = 0; ks < 2; ks++) { // two k16 steps, no barrier between
            const uint32_t ko = (uint32_t)(ks * 32);

            uint32_t ah[2][4], al[2][4];
#pragma unroll
            for (int tm = 0; tm < 2; tm++) {
                ldsm4(ah[tm], sb + aOffH + (uint32_t)(tm * 16 * PITCH) + ko);
                if (USE_AL)
                    ldsm4(al[tm], sb + aOffL + (uint32_t)(tm * 16 * PITCH) + ko);
            }
            uint32_t bh[8][2];
#pragma unroll
            for (int g = 0; g < 4; g++) {
                uint32_t t[4];
                ldsm4(t, sb + bOffH + (uint32_t)(g * 16 * PITCH) + ko);
                bh[2 * g][0] = t[0];     bh[2 * g][1] = t[2];
                bh[2 * g + 1][0] = t[1]; bh[2 * g + 1][1] = t[3];
            }
            // pass 1: ah * bh
#pragma unroll
            for (int tm = 0; tm < 2; tm++)
#pragma unroll
                for (int tn = 0; tn < 8; tn++)
                    mma16816(acc[tm][tn], ah[tm], bh[tn][0], bh[tn][1]);
            // pass 2: al * bh  (bh dies after this)
            if (USE_AL) {
#pragma unroll
                for (int tm = 0; tm < 2; tm++)
#pragma unroll
                    for (int tn = 0; tn < 8; tn++)
                        mma16816(acc[tm][tn], al[tm], bh[tn][0], bh[tn][1]);
            }
            // pass 3: ah * bl (bl loaded after bh is dead)
            if (USE_BL) {
                uint32_t bl[8][2];
#pragma unroll
                for (int g = 0; g < 4; g++) {
                    uint32_t t[4];
                    ldsm4(t, sb + bOffL + (uint32_t)(g * 16 * PITCH) + ko);
                    bl[2 * g][0] = t[0];     bl[2 * g][1] = t[2];
                    bl[2 * g + 1][0] = t[1]; bl[2 * g + 1][1] = t[3];
                }
#pragma unroll
                for (int tm = 0; tm < 2; tm++)
#pragma unroll
                    for (int tn = 0; tn < 8; tn++)
                        mma16816(acc[tm][tn], ah[tm], bl[tn][0], bl[tn][1]);
            }
        }

        __syncthreads();                 // all warps done reading stage kt&1
        if (kt + 2 < NKT) load_stage(kt & 1, kt + 2);
        CP_COMMIT();
    }

    // ---- epilogue ----
    const int mBase = M0 + wm * 32 + (lane >> 2);
    const int cBase = N0 + wn * 64 + (lane & 3) * 2;
#pragma unroll
    for (int tm = 0; tm < 2; tm++)
#pragma unroll
        for (int tn = 0; tn < 8; tn++) {
            const float* a = acc[tm][tn];
            const int m = mBase + tm * 16;
            const int c = cBase + tn * 8;
            const size_t o0 = (size_t)m * L + c;
            const size_t o1 = o0 + 8 * L;
            if (EPI == 0) {
                *reinterpret_cast<float2*>(&outF[o0]) =
                    make_float2(a[0] * scale, a[1] * scale);
                *reinterpret_cast<float2*>(&outF[o1]) =
                    make_float2(a[2] * scale, a[3] * scale);
            } else if (EPI == 1) {
#pragma unroll
                for (int p = 0; p < 2; p++) {
                    const float v0 = a[2 * p] * scale, v1 = a[2 * p + 1] * scale;
                    __half h0 = __float2half(v0);
                    __half h1 = __float2half(v1);
                    __half l0 = __float2half(v0 - __half2float(h0));
                    __half l1 = __float2half(v1 - __half2float(h1));
                    uint32_t hp = (uint32_t)__half_as_ushort(h0) |
                                  ((uint32_t)__half_as_ushort(h1) << 16);
                    uint32_t lp = (uint32_t)__half_as_ushort(l0) |
                                  ((uint32_t)__half_as_ushort(l1) << 16);
                    const size_t o = p ? o1 : o0;
                    *reinterpret_cast<uint32_t*>(&outHi[o]) = hp;
                    *reinterpret_cast<uint32_t*>(&outLo[o]) = lp;
                }
            } else {                      // EPI == 2: hi only
#pragma unroll
                for (int p = 0; p < 2; p++) {
                    const float v0 = a[2 * p] * scale, v1 = a[2 * p + 1] * scale;
                    uint32_t hp = (uint32_t)__half_as_ushort(__float2half(v0)) |
                                  ((uint32_t)__half_as_ushort(__float2half(v1)) << 16);
                    const size_t o = p ? o1 : o0;
                    *reinterpret_cast<uint32_t*>(&outHi[o]) = hp;
                }
            }
        }
}

// ---------------------------------------------------------------------------
// kernels (grid: x = L/BN = 8, y = L/BM = 8, z = batch)
// ---------------------------------------------------------------------------
__global__ void __launch_bounds__(256, 2)
g_kernel(const __half* __restrict__ WKNH, const __half* __restrict__ WKNL,
         const __half* __restrict__ WQNH, const __half* __restrict__ WQNL,
         __half* __restrict__ GH, __half* __restrict__ GL)
{
    // G = wk.wq^T; inputs x256 each -> store G*16 -> scale 1/4096. 3-pass.
    gemm_core<1, true, true>(WKNH, WKNL, WQNH, WQNL, 1.0f / 4096.0f,
                             nullptr, GH, GL);
}

__global__ void __launch_bounds__(256, 2)
t_kernel(const __half* __restrict__ XTH, const __half* __restrict__ XTL,
         const __half* __restrict__ GH, const __half* __restrict__ GL,
         __half* __restrict__ TTH, __half* __restrict__ TTL)
{
    // tT = xT.G16 (stores 16*t). 3-pass.
    const size_t bo = (size_t)blockIdx.z * PER_B;
    gemm_core<1, true, true>(XTH + bo, XTL + bo, GH, GL, 1.0f,
                             nullptr, TTH + bo, TTL + bo);
}

__global__ void __launch_bounds__(256, 2)
kq_kernel(const __half* __restrict__ XTH, const __half* __restrict__ XTL,
          const __half* __restrict__ TTH, const __half* __restrict__ TTL,
          float* __restrict__ outF)
{
    // kq = xT.tT16 / 512 (= x.t/32). 3-pass, fp32 out.
    const size_t bo = (size_t)blockIdx.z * PER_B;
    gemm_core<0, true, true>(XTH + bo, XTL + bo, TTH + bo, TTL + bo,
                             1.0f / 512.0f, outF + bo, nullptr, nullptr);
}

__global__ void __launch_bounds__(256, 2)
u_kernel(const __half* __restrict__ SMH, const __half* __restrict__ XNH,
         __half* __restrict__ UH)
{
    // u = sm.xN (stores 256*u, hi only). 1-pass.
    const size_t bo = (size_t)blockIdx.z * PER_B;
    gemm_core<2, false, false>(SMH + bo, nullptr, XNH + bo, nullptr, 256.0f,
                               nullptr, UH + bo, nullptr);
}

__global__ void __launch_bounds__(256, 2)
out_kernel(const __half* __restrict__ WVTH, const __half* __restrict__ UH,
           float* __restrict__ outF)
{
    // out = wvT256.u256 / 65536. 1-pass.
    const size_t bo = (size_t)blockIdx.z * PER_B;
    gemm_core<0, false, false>(WVTH, nullptr, UH + bo, nullptr,
                               1.0f / 65536.0f, outF + bo, nullptr, nullptr);
}

// ---------------------------------------------------------------------------
// Prep: z<16 -> x batch z: natural hi-only + transposed hi/lo (prescale 1).
//       z=16 -> wk natural x256 (hi/lo). z=17 -> wq natural x256 (hi/lo).
//       z=18 -> wv transposed x256 (hi only).
// ---------------------------------------------------------------------------
__global__ void __launch_bounds__(256)
prep_split(const float* __restrict__ x,
           const float* __restrict__ wk, const float* __restrict__ wq,
           const float* __restrict__ wv,
           __half* __restrict__ XTH, __half* __restrict__ XTL,
           __half* __restrict__ XNH,
           __half* __restrict__ WKNH, __half* __restrict__ WKNL,
           __half* __restrict__ WQNH, __half* __restrict__ WQNL,
           __half* __restrict__ WVTH)
{
    __shared__ float t[32][33];
    const int z = blockIdx.z;
    const int tx = threadIdx.x, ty = threadIdx.y;
    const int r0 = blockIdx.y * 32, c0 = blockIdx.x * 32;

    const float* in;
    float pres = 1.0f;
    bool natHi = false, natLo = false, trHi = false, trLo = false;
    __half *nh = nullptr, *nl = nullptr, *th = nullptr, *tl = nullptr;

    if (z < 16) {
        in = x + (size_t)z * PER_B;
        natHi = true;  trHi = true; trLo = true;
        nh = XNH + (size_t)z * PER_B;
        th = XTH + (size_t)z * PER_B; tl = XTL + (size_t)z * PER_B;
    } else if (z == 16) {
        in = wk; pres = W_PRESCALE; natHi = true; natLo = true;
        nh = WKNH; nl = WKNL;
    } else if (z == 17) {
        in = wq; pres = W_PRESCALE; natHi = true; natLo = true;
        nh = WQNH; nl = WQNL;
    } else {
        in = wv; pres = W_PRESCALE; trHi = true;
        th = WVTH;
    }

    float v[4];
#pragma unroll
    for (int i = 0; i < 4; i++)
        v[i] = in[(size_t)(r0 + ty + i * 8) * L + c0 + tx] * pres;

    if (natHi) {
#pragma unroll
        for (int i = 0; i < 4; i++) {
            __half h = __float2half(v[i]);
            size_t o = (size_t)(r0 + ty + i * 8) * L + c0 + tx;
            nh[o] = h;
            if (natLo) nl[o] = __float2half(v[i] - __half2float(h));
        }
    }
    if (trHi) {
#pragma unroll
        for (int i = 0; i < 4; i++) t[ty + i * 8][tx] = v[i];
        __syncthreads();
#pragma unroll
        for (int i = 0; i < 4; i++) {
            float vv = t[tx][ty + i * 8];
            __half h = __float2half(vv);
            size_t o = (size_t)(c0 + ty + i * 8) * L + r0 + tx;
            th[o] = h;
            if (trLo) tl[o] = __float2half(vv - __half2float(h));
        }
    }
}

// ---------------------------------------------------------------------------
// row softmax (1024 wide), output single-digit fp16
// ---------------------------------------------------------------------------
__global__ void __launch_bounds__(256)
softmax_h(const float* __restrict__ kq, __half* __restrict__ oh)
{
    const size_t rb = (size_t)blockIdx.x * L;
    const int tid = threadIdx.x;
    float4 v = *reinterpret_cast<const float4*>(&kq[rb + tid * 4]);

    __shared__ float red[8];
    const int lane = tid & 31, wid = tid >> 5;

    float m = fmaxf(fmaxf(v.x, v.y), fmaxf(v.z, v.w));
#pragma unroll
    for (int o = 16; o; o >>= 1) m = fmaxf(m, __shfl_xor_sync(0xffffffffu, m, o));
    if (lane == 0) red[wid] = m;
    __syncthreads();
    m = red[0];
#pragma unroll
    for (int w = 1; w < 8; w++) m = fmaxf(m, red[w]);
    __syncthreads();

    v.x = expf(v.x - m); v.y = expf(v.y - m);
    v.z = expf(v.z - m); v.w = expf(v.w - m);
    float s = v.x + v.y + v.z + v.w;
#pragma unroll
    for (int o = 16; o; o >>= 1) s += __shfl_xor_sync(0xffffffffu, s, o);
    if (lane == 0) red[wid] = s;
    __syncthreads();
    s = red[0];
#pragma unroll
    for (int w = 1; w < 8; w++) s += red[w];

    const float inv = 1.0f / s;
    uint32_t p0 = (uint32_t)__half_as_ushort(__float2half(v.x * inv)) |
                  ((uint32_t)__half_as_ushort(__float2half(v.y * inv)) << 16);
    uint32_t p1 = (uint32_t)__half_as_ushort(__float2half(v.z * inv)) |
                  ((uint32_t)__half_as_ushort(__float2half(v.w * inv)) << 16);
    *reinterpret_cast<uint2*>(&oh[rb + tid * 4]) = make_uint2(p0, p1);
}

// ---------------------------------------------------------------------------
// host
// ---------------------------------------------------------------------------
extern "C" void kernel_launch(void* const* d_in, const int* in_sizes, int n_in,
                              void* d_out, int out_size)
{
    (void)in_sizes; (void)n_in; (void)out_size;
    const float* x  = (const float*)d_in[0];
    const float* wk = (const float*)d_in[1];
    const float* wq = (const float*)d_in[2];
    const float* wv = (const float*)d_in[3];
    float* out = (float*)d_out;

    void *xth, *xtl, *xnh, *tth, *ttl, *smh, *uh;
    void *gh, *gl, *wknh, *wknl, *wqnh, *wqnl, *wvth, *kq;
    cudaGetSymbolAddress(&xth, g_xT_hi);  cudaGetSymbolAddress(&xtl, g_xT_lo);
    cudaGetSymbolAddress(&xnh, g_xN_hi);
    cudaGetSymbolAddress(&tth, g_tT_hi);  cudaGetSymbolAddress(&ttl, g_tT_lo);
    cudaGetSymbolAddress(&smh, g_sm_hi);
    cudaGetSymbolAddress(&uh, g_u_hi);
    cudaGetSymbolAddress(&gh, g_G_hi);    cudaGetSymbolAddress(&gl, g_G_lo);
    cudaGetSymbolAddress(&wknh, g_wkN_hi); cudaGetSymbolAddress(&wknl, g_wkN_lo);
    cudaGetSymbolAddress(&wqnh, g_wqN_hi); cudaGetSymbolAddress(&wqnl, g_wqN_lo);
    cudaGetSymbolAddress(&wvth, g_wvT_hi);
    cudaGetSymbolAddress(&kq, g_kq);

    cudaFuncSetAttribute((const void*)g_kernel,
                         cudaFuncAttributeMaxDynamicSharedMemorySize, SMEM_DYN);
    cudaFuncSetAttribute((const void*)t_kernel,
                         cudaFuncAttributeMaxDynamicSharedMemorySize, SMEM_DYN);
    cudaFuncSetAttribute((const void*)kq_kernel,
                         cudaFuncAttributeMaxDynamicSharedMemorySize, SMEM_DYN);
    cudaFuncSetAttribute((const void*)u_kernel,
                         cudaFuncAttributeMaxDynamicSharedMemorySize, SMEM_DYN);
    cudaFuncSetAttribute((const void*)out_kernel,
                         cudaFuncAttributeMaxDynamicSharedMemorySize, SMEM_DYN);

    // prep: x -> XT (hi/lo) + XN (hi); wk,wq natural hi/lo; wv transposed hi
    prep_split<<<dim3(32, 32, 19), dim3(32, 8)>>>(
        x, wk, wq, wv,
        (__half*)xth, (__half*)xtl, (__half*)xnh,
        (__half*)wknh, (__half*)wknl, (__half*)wqnh, (__half*)wqnl,
        (__half*)wvth);

    const dim3 gg(L / BN, L / BM, BATCH);     // 8 x 8 x 16

    // G = wk.wq^T (unbatched)
    g_kernel<<<dim3(L / BN, L / BM, 1), 256, SMEM_DYN>>>(
        (__half*)wknh, (__half*)wknl, (__half*)wqnh, (__half*)wqnl,
        (__half*)gh, (__half*)gl);

    // tT = xT . G
    t_kernel<<<gg, 256, SMEM_DYN>>>(
        (__half*)xth, (__half*)xtl, (__half*)gh, (__half*)gl,
        (__half*)tth, (__half*)ttl);

    // kq = xT . tT / 32
    kq_kernel<<<gg, 256, SMEM_DYN>>>(
        (__half*)xth, (__half*)xtl, (__half*)tth, (__half*)ttl, (float*)kq);

    // softmax -> sm (1 digit)
    softmax_h<<<BATCH * L, 256>>>((const float*)kq, (__half*)smh);

    // u = sm . xN  (1-pass)
    u_kernel<<<gg, 256, SMEM_DYN>>>((__half*)smh, (__half*)xnh, (__half*)uh);

    // out = wvT . u  (1-pass)
    out_kernel<<<gg, 256, SMEM_DYN>>>((__half*)wvth, (__half*)uh, out);
}